// round 13
// baseline (speedup 1.0000x reference)
#include <cuda_runtime.h>
#include <cuda_fp16.h>
#include <math.h>
#include <stdint.h>

// Problem dims (fixed by reference)
#define TT 128
#define BB 128
#define SS 128
#define HH 1024
#define EE 512
#define FH 4096   // 4*H
#define VV 32000

#define INV2048 4.8828125e-4f

// ---------------------------------------------------------------------------
// Scratch (device globals: allocation-free contract)
// ---------------------------------------------------------------------------
__device__ float g_gin0[(size_t)TT * BB * FH];
__device__ float g_h0[BB * HH];
__device__ float g_c0[BB * HH];
__device__ float g_h1[BB * HH];
__device__ float g_c1[BB * HH];
__device__ float g_gamma[BB * HH];

// fp16 split buffers: x = hi + lo/2048  (lo stored pre-scaled by 2048)
__device__ half g_embh [(size_t)VV * EE];
__device__ half g_embl [(size_t)VV * EE];
__device__ half g_Wih0h[(size_t)FH * EE];
__device__ half g_Wih0l[(size_t)FH * EE];
__device__ half g_Whh0h[(size_t)FH * HH];
__device__ half g_Whh0l[(size_t)FH * HH];
__device__ half g_Wih1h[(size_t)FH * HH];
__device__ half g_Wih1l[(size_t)FH * HH];
__device__ half g_Whh1h[(size_t)FH * HH];
__device__ half g_Whh1l[(size_t)FH * HH];
__device__ half g_attWh[(size_t)HH * HH];
__device__ half g_attWl[(size_t)HH * HH];
__device__ half g_outWh[(size_t)HH * 2 * HH];
__device__ half g_outWl[(size_t)HH * 2 * HH];

// h0 pairs: parity double-buffer (P1(k) writes parity k&1; initial in parity 1)
__device__ half g_h0h0[BB * HH];
__device__ half g_h0l0[BB * HH];
__device__ half g_h0h1[BB * HH];
__device__ half g_h0l1[BB * HH];
// h1 pairs: 3-buffer mod 3 (P2(t) writes t%3; initial state in buf 2)
__device__ half g_h1hA[BB * HH];
__device__ half g_h1lA[BB * HH];
__device__ half g_h1hB[BB * HH];
__device__ half g_h1lB[BB * HH];
__device__ half g_h1hC[BB * HH];
__device__ half g_h1lC[BB * HH];
__device__ half g_ctxh[BB * HH];
__device__ half g_ctxl[BB * HH];

__device__ unsigned int g_barA;   // group-A barrier counter
__device__ unsigned int g_barB;   // group-B barrier counter
__device__ unsigned int g_cP1;    // B progress: +1/block after P1(k)   -> 64(k+1)
__device__ unsigned int g_cA;     // A progress: +1/block after P2(t)   -> 64(t+1)
__device__ unsigned int g_cAT;    // B progress: +1/block after attn(v) -> 64(v+1)

__device__ __forceinline__ float sigmoidf_(float x) {
    return 1.0f / (1.0f + __expf(-x));
}

__device__ __forceinline__ void split16(float x, half* h, half* l) {
    const half hh = __float2half_rn(x);
    *h = hh;
    *l = __float2half_rn((x - __half2float(hh)) * 2048.0f);
}

__device__ __forceinline__ uint32_t smem_u32(const void* p) {
    uint32_t a;
    asm("{ .reg .u64 t; cvta.to.shared.u64 t, %1; cvt.u32.u64 %0, t; }"
        : "=r"(a) : "l"(p));
    return a;
}

__device__ __forceinline__ void ldm4(uint32_t* r, uint32_t a) {
    asm volatile("ldmatrix.sync.aligned.m8n8.x4.shared.b16 {%0,%1,%2,%3}, [%4];"
                 : "=r"(r[0]), "=r"(r[1]), "=r"(r[2]), "=r"(r[3]) : "r"(a));
}

__device__ __forceinline__ void ldm2(uint32_t* r, uint32_t a) {
    asm volatile("ldmatrix.sync.aligned.m8n8.x2.shared.b16 {%0,%1}, [%2];"
                 : "=r"(r[0]), "=r"(r[1]) : "r"(a));
}

__device__ __forceinline__ void mma_f16(float* d, const uint32_t* a, const uint32_t* b) {
    asm volatile(
        "mma.sync.aligned.m16n8k16.row.col.f32.f16.f16.f32 "
        "{%0,%1,%2,%3}, {%4,%5,%6,%7}, {%8,%9}, {%0,%1,%2,%3};\n"
        : "+f"(d[0]), "+f"(d[1]), "+f"(d[2]), "+f"(d[3])
        : "r"(a[0]), "r"(a[1]), "r"(a[2]), "r"(a[3]), "r"(b[0]), "r"(b[1]));
}

__device__ __forceinline__ void cp16(void* smem, const void* gmem) {   // L1 (static)
    asm volatile("cp.async.ca.shared.global [%0], [%1], 16;"
                 :: "r"(smem_u32(smem)), "l"(gmem));
}

__device__ __forceinline__ void cp16cg(void* smem, const void* gmem) { // L2-only (dynamic)
    asm volatile("cp.async.cg.shared.global [%0], [%1], 16;"
                 :: "r"(smem_u32(smem)), "l"(gmem));
}

// Group barrier (R10-proven).
__device__ __forceinline__ void group_sync(unsigned int* bar, unsigned int target) {
    __syncthreads();
    __threadfence();
    if (threadIdx.x == 0) {
        atomicAdd(bar, 1u);
        unsigned int v;
        do {
            asm volatile("ld.acquire.gpu.u32 %0, [%1];"
                         : "=r"(v) : "l"(bar) : "memory");
        } while (v < target);
    }
    __syncthreads();
}

__device__ __forceinline__ void wait_cnt(unsigned int* cnt, unsigned int target) {
    if (threadIdx.x == 0) {
        unsigned int v;
        do {
            asm volatile("ld.acquire.gpu.u32 %0, [%1];"
                         : "=r"(v) : "l"(cnt) : "memory");
        } while (v < target);
    }
    __syncthreads();
}

__device__ __forceinline__ void bump_cnt(unsigned int* cnt) {
    __syncthreads();
    __threadfence();
    if (threadIdx.x == 0) atomicAdd(cnt, 1u);
}

// Smem tile layout: rows of 16 halves (32 B); chunk c of row r at
// r*32 + ((c ^ ((r>>2)&1))<<4)  -> conflict-free stores + ldmatrix.
__device__ __forceinline__ uint32_t swz(int row, int c) {
    return (uint32_t)(row * 32 + ((c ^ ((row >> 2) & 1)) << 4));
}

// ---------------------------------------------------------------------------
// Prologue: split weights/emb, init state, reset counters.
// h0 initial -> parity 1; h1 initial -> buf C (index 2).
// ---------------------------------------------------------------------------
__global__ void prologue_kernel(
    const float* __restrict__ emb,
    const float* __restrict__ W_ih0, const float* __restrict__ W_hh0,
    const float* __restrict__ W_ih1, const float* __restrict__ W_hh1,
    const float* __restrict__ attW,  const float* __restrict__ outW,
    const float* __restrict__ h0,    const float* __restrict__ c0)
{
    if (blockIdx.x == 0 && threadIdx.x == 0) {
        g_barA = 0u; g_barB = 0u; g_cP1 = 0u; g_cA = 0u; g_cAT = 0u;
    }

    const long nE = (long)VV * EE;
    const long n0 = (long)FH * EE, n1 = (long)FH * HH;
    const long n4 = (long)HH * HH, n5 = (long)HH * 2 * HH;
    const long nS = BB * HH;
    const long total = nE + n0 + 3 * n1 + n4 + n5 + nS;
    for (long i = (long)blockIdx.x * blockDim.x + threadIdx.x; i < total;
         i += (long)gridDim.x * blockDim.x) {
        long j = i;
        if (j < nE) { split16(emb[j],   &g_embh[j],  &g_embl[j]);  continue; } j -= nE;
        if (j < n0) { split16(W_ih0[j], &g_Wih0h[j], &g_Wih0l[j]); continue; } j -= n0;
        if (j < n1) { split16(W_hh0[j], &g_Whh0h[j], &g_Whh0l[j]); continue; } j -= n1;
        if (j < n1) { split16(W_ih1[j], &g_Wih1h[j], &g_Wih1l[j]); continue; } j -= n1;
        if (j < n1) { split16(W_hh1[j], &g_Whh1h[j], &g_Whh1l[j]); continue; } j -= n1;
        if (j < n4) { split16(attW[j],  &g_attWh[j], &g_attWl[j]); continue; } j -= n4;
        if (j < n5) { split16(outW[j],  &g_outWh[j], &g_outWl[j]); continue; } j -= n5;
        const float a  = h0[j];
        const float b2 = h0[BB * HH + j];
        g_h0[j] = a;  g_h1[j] = b2;
        g_c0[j] = c0[j];  g_c1[j] = c0[BB * HH + j];
        split16(a,  &g_h0h1[j], &g_h0l1[j]);   // h0 initial -> parity 1
        split16(b2, &g_h1hC[j], &g_h1lC[j]);   // h1 initial -> buf 2
    }
}

// ---------------------------------------------------------------------------
// gin0 GEMM (unchanged, proven): emb[inputs]·W_ih0^T + biases.
// ---------------------------------------------------------------------------
__global__ __launch_bounds__(128)
void gin0_gemm_kernel(const int* __restrict__ gidx,
                      const float* __restrict__ bias1,
                      const float* __restrict__ bias2)
{
    constexpr int STRIDE = 6144;
    __shared__ __align__(16) char sm[4 * STRIDE];

    const int tid  = threadIdx.x;
    const int lane = tid & 31;
    const int warp = tid >> 5;
    const int wm = (warp >> 1) * 32;
    const int wn = (warp & 1) * 16;
    const int row0 = blockIdx.y * 64;
    const int col0 = blockIdx.x * 32;
    const uint32_t sbase = smem_u32(sm);

    uint32_t aoff[2];
#pragma unroll
    for (int mi = 0; mi < 2; mi++) {
        const int r = wm + mi * 16 + ((lane >> 3) & 1) * 8 + (lane & 7);
        aoff[mi] = swz(r, lane >> 4);
    }
    uint32_t boff;
    {
        const int m = lane >> 3;
        const int n = wn + (m >> 1) * 8 + (lane & 7);
        boff = swz(n, m & 1);
    }

    const int arow = tid >> 1, ac = tid & 1;
    const uint32_t asw = swz(arow, ac);
    const int bcomp = tid >> 6;
    const int bn = (tid & 63) >> 1, bc = tid & 1;
    const uint32_t bsw = swz(bn, bc) + (bcomp ? 1024u : 0u);

    float D1[2][2][4], D2[2][2][4];
#pragma unroll
    for (int mi = 0; mi < 2; mi++)
#pragma unroll
        for (int ni = 0; ni < 2; ni++)
#pragma unroll
            for (int q = 0; q < 4; q++) { D1[mi][ni][q] = 0.f; D2[mi][ni][q] = 0.f; }

#define G0LOAD(buf_, k0_)                                                        \
    do {                                                                         \
        const size_t ro = (size_t)gidx[row0 + arow] * EE;                        \
        cp16(sm + (buf_)*STRIDE + asw,        g_embh + ro + (k0_) + ac * 8);     \
        cp16(sm + (buf_)*STRIDE + 2048 + asw, g_embl + ro + (k0_) + ac * 8);     \
        {                                                                        \
            const half* wb = bcomp ? g_Wih0l : g_Wih0h;                          \
            cp16(sm + (buf_)*STRIDE + 4096 + bsw,                                \
                 wb + (size_t)(col0 + bn) * EE + (k0_) + bc * 8);                \
        }                                                                        \
    } while (0)

#define G0MMA(buf_)                                                              \
    do {                                                                         \
        const uint32_t st = sbase + (buf_)*STRIDE;                               \
        uint32_t bhv[4], blv[4];                                                 \
        ldm4(bhv, st + 4096 + boff);                                             \
        ldm4(blv, st + 5120 + boff);                                             \
        _Pragma("unroll")                                                        \
        for (int mi = 0; mi < 2; mi++) {                                         \
            uint32_t ah[4], al_[4];                                              \
            ldm4(ah,  st + aoff[mi]);                                            \
            ldm4(al_, st + 2048 + aoff[mi]);                                     \
            _Pragma("unroll")                                                    \
            for (int ni = 0; ni < 2; ni++) {                                     \
                mma_f16(D1[mi][ni], ah,  bhv + 2 * ni);                          \
                mma_f16(D2[mi][ni], ah,  blv + 2 * ni);                          \
                mma_f16(D2[mi][ni], al_, bhv + 2 * ni);                          \
            }                                                                    \
        }                                                                        \
    } while (0)

    const int niter = EE >> 4;
#pragma unroll
    for (int p = 0; p < 3; ++p) {
        G0LOAD(p, p << 4);
        asm volatile("cp.async.commit_group;");
    }
    for (int it0 = 0; it0 < niter; it0 += 4) {
#pragma unroll
        for (int sb = 0; sb < 4; sb++) {
            const int it = it0 + sb;
            const int nx = it + 3;
            constexpr int nlut[4] = {3, 0, 1, 2};
            if (nx < niter) G0LOAD(nlut[sb], nx << 4);
            asm volatile("cp.async.commit_group;");
            asm volatile("cp.async.wait_group 3;");
            __syncthreads();
            G0MMA(sb);
            __syncthreads();
        }
    }
#undef G0LOAD
#undef G0MMA

#pragma unroll
    for (int mi = 0; mi < 2; mi++) {
#pragma unroll
        for (int ni = 0; ni < 2; ni++) {
            const int c = col0 + wn + ni * 8 + 2 * (lane & 3);
#pragma unroll
            for (int hr = 0; hr < 2; hr++) {
                const int r = row0 + wm + mi * 16 + (lane >> 2) + 8 * hr;
                float v0 = D1[mi][ni][2*hr+0] + D2[mi][ni][2*hr+0] * INV2048
                           + bias1[c] + bias2[c];
                float v1 = D1[mi][ni][2*hr+1] + D2[mi][ni][2*hr+1] * INV2048
                           + bias1[c+1] + bias2[c+1];
                *reinterpret_cast<float2*>(&g_gin0[(size_t)r * FH + c]) =
                    make_float2(v0, v1);
            }
        }
    }
}

// ---------------------------------------------------------------------------
// Fused gates-GEMM + cell, BN=64 tiles (R12-proven internals).
// ---------------------------------------------------------------------------
__device__ void gates64_phase(char* dsm, int tileid,
    const half* __restrict__ A1h, const half* __restrict__ A1l,
    const half* __restrict__ W1h, const half* __restrict__ W1l, int K1,
    const half* __restrict__ A2h, const half* __restrict__ A2l,
    const half* __restrict__ W2h, const half* __restrict__ W2l, int K2,
    const float* __restrict__ bias1, const float* __restrict__ bias2,
    const float* __restrict__ gin,
    float* __restrict__ h, float* __restrict__ c,
    half* __restrict__ hph, half* __restrict__ hpl)
{
    constexpr int STRIDE = 12288;
    const int tid  = threadIdx.x;
    const int lane = tid & 31;
    const int warp = tid >> 5;
    const int wm   = warp * 16;
    const int j0   = tileid * 16;
    const uint32_t sbase = smem_u32(dsm);

    const int ar = wm + ((lane >> 3) & 1) * 8 + (lane & 7);
    const uint32_t aoff = swz(ar, lane >> 4);
    uint32_t boff[4];
#pragma unroll
    for (int p = 0; p < 4; p++) {
        const int m = lane >> 3;
        const int n = (2 * p + (m >> 1)) * 8 + (lane & 7);
        boff[p] = swz(n, m & 1);
    }

    const int arow = tid >> 1, ac = tid & 1;
    const uint32_t asw = swz(arow, ac);
    const int bcomp = tid >> 7;
    const int bn = (tid & 127) >> 1, bc = tid & 1;
    const int wrow = (bn >> 4) * HH + j0 + (bn & 15);
    const uint32_t bsw = swz(bn, bc) + (bcomp ? 2048u : 0u);

    float D1[8][4], D2[8][4];
#pragma unroll
    for (int ni = 0; ni < 8; ni++)
#pragma unroll
        for (int q = 0; q < 4; q++) { D1[ni][q] = 0.f; D2[ni][q] = 0.f; }

#define GLOAD(buf_, k0_)                                                          \
    do {                                                                          \
        cp16cg(dsm + (buf_)*STRIDE + asw,        Ah_ + (size_t)arow*K + (k0_) + ac*8); \
        cp16cg(dsm + (buf_)*STRIDE + 4096 + asw, Al_ + (size_t)arow*K + (k0_) + ac*8); \
        {                                                                         \
            const half* wb = bcomp ? Wl_ : Wh_;                                   \
            cp16(dsm + (buf_)*STRIDE + 8192 + bsw,                                \
                 wb + (size_t)wrow * K + (k0_) + bc * 8);                         \
        }                                                                         \
    } while (0)

#define GMMA(buf_)                                                               \
    do {                                                                         \
        const uint32_t st = sbase + (buf_)*STRIDE;                               \
        uint32_t ah[4], al_[4];                                                  \
        ldm4(ah,  st + aoff);                                                    \
        ldm4(al_, st + 4096 + aoff);                                             \
        _Pragma("unroll")                                                        \
        for (int p = 0; p < 4; p++) {                                            \
            uint32_t bhv[4], blv[4];                                             \
            ldm4(bhv, st + 8192  + boff[p]);                                     \
            ldm4(blv, st + 10240 + boff[p]);                                     \
            _Pragma("unroll")                                                    \
            for (int w2 = 0; w2 < 2; w2++) {                                     \
                const int ni = 2 * p + w2;                                       \
                mma_f16(D1[ni], ah,  bhv + 2 * w2);                              \
                mma_f16(D2[ni], ah,  blv + 2 * w2);                              \
                mma_f16(D2[ni], al_, bhv + 2 * w2);                              \
            }                                                                    \
        }                                                                        \
    } while (0)

    for (int s = 0; s < 2; ++s) {
        const half* Ah_ = s ? A2h : A1h;
        if (Ah_ == nullptr) continue;
        const half* Al_ = s ? A2l : A1l;
        const half* Wh_ = s ? W2h : W1h;
        const half* Wl_ = s ? W2l : W1l;
        const int K     = s ? K2 : K1;
        const int niter = K >> 4;

#pragma unroll
        for (int p = 0; p < 3; ++p) {
            GLOAD(p, p << 4);
            asm volatile("cp.async.commit_group;");
        }
        for (int it0 = 0; it0 < niter; it0 += 4) {
#pragma unroll
            for (int sb = 0; sb < 4; sb++) {
                const int it = it0 + sb;
                const int nx = it + 3;
                constexpr int nlut[4] = {3, 0, 1, 2};
                if (nx < niter) GLOAD(nlut[sb], nx << 4);
                asm volatile("cp.async.commit_group;");
                asm volatile("cp.async.wait_group 3;");
                __syncthreads();
                GMMA(sb);
                __syncthreads();
            }
        }
    }
#undef GLOAD
#undef GMMA

    const int jl2 = 2 * (lane & 3);
#pragma unroll
    for (int hf = 0; hf < 2; hf++) {
        const int r = wm + (lane >> 2) + 8 * hf;
#pragma unroll
        for (int o = 0; o < 2; o++) {
#pragma unroll
            for (int e = 0; e < 2; e++) {
                const int q  = 2 * hf + e;
                const int jg = j0 + 8 * o + jl2 + e;
                float gi = D1[0 + o][q] + D2[0 + o][q] * INV2048;
                float gf = D1[2 + o][q] + D2[2 + o][q] * INV2048;
                float gg = D1[4 + o][q] + D2[4 + o][q] * INV2048;
                float go = D1[6 + o][q] + D2[6 + o][q] * INV2048;
                if (bias1) {
                    gi += bias1[jg];            gf += bias1[HH + jg];
                    gg += bias1[2 * HH + jg];   go += bias1[3 * HH + jg];
                }
                if (bias2) {
                    gi += bias2[jg];            gf += bias2[HH + jg];
                    gg += bias2[2 * HH + jg];   go += bias2[3 * HH + jg];
                }
                if (gin) {
                    const float* gr = gin + (size_t)r * FH;
                    gi += gr[jg];          gf += gr[HH + jg];
                    gg += gr[2 * HH + jg]; go += gr[3 * HH + jg];
                }
                const int idx = r * HH + jg;
                const float cn = sigmoidf_(gf) * c[idx] + sigmoidf_(gi) * tanhf(gg);
                const float hn = sigmoidf_(go) * tanhf(cn);
                c[idx] = cn;
                h[idx] = hn;
                split16(hn, &hph[idx], &hpl[idx]);
            }
        }
    }
}

// ---------------------------------------------------------------------------
// 32x32-tile GEMM (R11/12-proven internals).
// ---------------------------------------------------------------------------
__device__ void gemm32_phase(char* dsm, int tile,
    const half* __restrict__ A1h, const half* __restrict__ A1l, int lda1,
    const half* __restrict__ B1h, const half* __restrict__ B1l, int ldb1, int K1,
    const half* __restrict__ A2h, const half* __restrict__ A2l, int lda2,
    const half* __restrict__ B2h, const half* __restrict__ B2l, int ldb2, int K2,
    const float* __restrict__ bias,
    float* __restrict__ C, int ldc, int act)
{
    constexpr int STRIDE = 4096;
    const int tid  = threadIdx.x;
    const int lane = tid & 31;
    const int warp = tid >> 5;
    const int wm = (warp >> 2) * 16;
    const int wn = (warp & 3) * 8;
    const int row0 = (tile >> 5) * 32;
    const int col0 = (tile & 31) * 32;
    const uint32_t sbase = smem_u32(dsm);

    const int ar = wm + ((lane >> 3) & 1) * 8 + (lane & 7);
    const uint32_t aoff = swz(ar, lane >> 4);
    uint32_t boff;
    {
        const int m = (lane & 15) >> 3;
        const int n = wn + (lane & 7);
        boff = swz(n, m);
    }

    const int reg4 = tid >> 6;
    const int lrow = (tid & 63) >> 1, lc = tid & 1;
    const uint32_t lsw = swz(lrow, lc) + (uint32_t)reg4 * 1024u;

    float D1[4] = {0.f, 0.f, 0.f, 0.f};
    float D2[4] = {0.f, 0.f, 0.f, 0.f};

#define LT32(buf_, k0_)                                                           \
    do {                                                                          \
        if (reg4 < 2) {                                                           \
            const half* ab = reg4 ? Al_ : Ah_;                                    \
            cp16cg(dsm + (buf_)*STRIDE + lsw,                                     \
                   ab + (size_t)(row0 + lrow) * lda + (k0_) + lc * 8);            \
        } else {                                                                  \
            const half* bb = (reg4 == 3) ? Bl_ : Bh_;                             \
            cp16(dsm + (buf_)*STRIDE + lsw,                                       \
                 bb + (size_t)(col0 + lrow) * ldb + (k0_) + lc * 8);              \
        }                                                                         \
    } while (0)

#define MS32(buf_)                                                                \
    do {                                                                          \
        const uint32_t st = sbase + (buf_)*STRIDE;                                \
        uint32_t ah[4], al_[4], bh[2], bl[2];                                     \
        ldm4(ah,  st + aoff);                                                     \
        ldm4(al_, st + 1024 + aoff);                                              \
        ldm2(bh,  st + 2048 + boff);                                              \
        ldm2(bl,  st + 3072 + boff);                                              \
        mma_f16(D1, ah,  bh);                                                     \
        mma_f16(D2, ah,  bl);                                                     \
        mma_f16(D2, al_, bh);                                                     \
    } while (0)

    for (int s = 0; s < 2; ++s) {
        const half* Ah_ = s ? A2h : A1h;
        if (Ah_ == nullptr) continue;
        const half* Al_ = s ? A2l : A1l;
        const half* Bh_ = s ? B2h : B1h;
        const half* Bl_ = s ? B2l : B1l;
        const int lda = s ? lda2 : lda1;
        const int ldb = s ? ldb2 : ldb1;
        const int K   = s ? K2 : K1;
        const int niter = K >> 4;

#pragma unroll
        for (int p = 0; p < 3; ++p) {
            LT32(p, p << 4);
            asm volatile("cp.async.commit_group;");
        }
        for (int it0 = 0; it0 < niter; it0 += 4) {
#pragma unroll
            for (int sb = 0; sb < 4; sb++) {
                const int it = it0 + sb;
                const int nx = it + 3;
                constexpr int nlut[4] = {3, 0, 1, 2};
                if (nx < niter) LT32(nlut[sb], nx << 4);
                asm volatile("cp.async.commit_group;");
                asm volatile("cp.async.wait_group 3;");
                __syncthreads();
                MS32(sb);
                __syncthreads();
            }
        }
    }
#undef LT32
#undef MS32

    const int cc = col0 + wn + 2 * (lane & 3);
#pragma unroll
    for (int hf = 0; hf < 2; hf++) {
        const int r = row0 + wm + (lane >> 2) + 8 * hf;
        float v0 = D1[2*hf+0] + D2[2*hf+0] * INV2048 + bias[cc];
        float v1 = D1[2*hf+1] + D2[2*hf+1] * INV2048 + bias[cc+1];
        if (act == 1) { v0 = tanhf(v0); v1 = tanhf(v1); }
        *reinterpret_cast<float2*>(&C[(size_t)r * (size_t)ldc + cc]) =
            make_float2(v0, v1);
    }
}

// ---------------------------------------------------------------------------
// Attention phase (R11/12-proven internals).
// ---------------------------------------------------------------------------
__device__ void attention_phase(char* dsmc,
                                const float* __restrict__ contexts,
                                const float* __restrict__ gamma,
                                half* __restrict__ ctxh,
                                half* __restrict__ ctxl, int b)
{
    float* sg     = reinterpret_cast<float*>(dsmc);
    float* sw     = sg + HH;
    float* red    = sw + SS;
    float* s_stat = red + 8;

    const int tid  = threadIdx.x;
    const int lane = tid & 31;
    const int warp = tid >> 5;
    const float* cb = contexts + (size_t)b * SS * HH;

    for (int j = tid; j < HH; j += 256) sg[j] = __ldcg(&gamma[(size_t)b * HH + j]);
    __syncthreads();

    for (int s = warp; s < SS; s += 8) {
        const float* cr = cb + (size_t)s * HH;
        float sum = 0.0f;
#pragma unroll 4
        for (int j = lane * 4; j < HH; j += 128) {
            float4 v = *reinterpret_cast<const float4*>(&cr[j]);
            sum = fmaf(v.x, sg[j], sum);
            sum = fmaf(v.y, sg[j + 1], sum);
            sum = fmaf(v.z, sg[j + 2], sum);
            sum = fmaf(v.w, sg[j + 3], sum);
        }
#pragma unroll
        for (int off = 16; off; off >>= 1)
            sum += __shfl_xor_sync(0xffffffffu, sum, off);
        if (lane == 0) sw[s] = sum;
    }
    __syncthreads();

    const float v = (tid < SS) ? sw[tid] : -3.4e38f;
    float m = v;
#pragma unroll
    for (int off = 16; off; off >>= 1)
        m = fmaxf(m, __shfl_xor_sync(0xffffffffu, m, off));
    if (lane == 0) red[warp] = m;
    __syncthreads();
    if (tid == 0) {
        float mm = red[0];
        for (int w2 = 1; w2 < 8; w2++) mm = fmaxf(mm, red[w2]);
        *s_stat = mm;
    }
    __syncthreads();
    const float bm = *s_stat;
    const float e = (tid < SS) ? __expf(v - bm) : 0.0f;
    float s2 = e;
#pragma unroll
    for (int off = 16; off; off >>= 1)
        s2 += __shfl_xor_sync(0xffffffffu, s2, off);
    if (lane == 0) red[warp] = s2;
    __syncthreads();
    if (tid == 0) {
        float t = 0.0f;
        for (int w2 = 0; w2 < 8; w2++) t += red[w2];
        *s_stat = 1.0f / t;
    }
    __syncthreads();
    if (tid < SS) sw[tid] = e * (*s_stat);
    __syncthreads();

    float acc[4] = {0.0f, 0.0f, 0.0f, 0.0f};
    for (int s = 0; s < SS; s++) {
        const float w = sw[s];
        const float* cr = cb + (size_t)s * HH;
#pragma unroll
        for (int q = 0; q < 4; q++)
            acc[q] = fmaf(w, cr[tid + q * 256], acc[q]);
    }
#pragma unroll
    for (int q = 0; q < 4; q++) {
        const int idx = b * HH + tid + q * 256;
        split16(acc[q], &ctxh[idx], &ctxl[idx]);
    }
}

// ---------------------------------------------------------------------------
// Persistent kernel: pipelined two-group schedule.
//  Cycle k:  B (blocks 64-127): P1(k) [k<TT]  +  attn(k-2) [k>=2]
//            A (blocks 0-63):   P2(k-1)       [1<=k<=TT]
//  h0 pairs: parity (P1(k) -> k&1).  h1 pairs: mod-3 (P2(t) -> t%3).
//  Counters: cP1 (after P1), cA (after P2), cAT (after attn P5).
// ---------------------------------------------------------------------------
__global__ __launch_bounds__(256)
void persistent_kernel(const float* __restrict__ b_ih1,
                       const float* __restrict__ b_hh1,
                       const float* __restrict__ attb,
                       const float* __restrict__ outb,
                       const float* __restrict__ contexts,
                       float* __restrict__ out)
{
    extern __shared__ __align__(16) char dsm[];
    const int bid = blockIdx.x;

    half* const h1h[3] = { g_h1hA, g_h1hB, g_h1hC };
    half* const h1l[3] = { g_h1lA, g_h1lB, g_h1lC };

    if (bid < 64) {
        // ---------------- Group A: P2(t) for t = 0..TT-1 ----------------
        unsigned int tA = 0;
        for (int t = 0; t < TT; t++) {
            // h0p[par t] ready: P1(t) done
            wait_cnt(&g_cP1, 64u * (unsigned)(t + 1));
            // overwrite h1 buf t%3: attn(t-3) must be done
            if (t >= 3) wait_cnt(&g_cAT, 64u * (unsigned)(t - 2));

            const half* a1h = (t & 1) ? g_h0h1 : g_h0h0;
            const half* a1l = (t & 1) ? g_h0l1 : g_h0l0;
            const int rb = (t + 2) % 3;     // (t-1) mod 3
            const int wb = t % 3;

            gates64_phase(dsm, bid,
                          a1h, a1l, g_Wih1h, g_Wih1l, HH,
                          h1h[rb], h1l[rb], g_Whh1h, g_Whh1l, HH,
                          b_ih1, b_hh1,
                          nullptr,
                          g_h1, g_c1, h1h[wb], h1l[wb]);
            tA += 64; group_sync(&g_barA, tA);
            bump_cnt(&g_cA);
        }
        // final h1 / c1 (layer-1 rows of hT/cT)
        float* o2 = out + (size_t)TT * BB * HH;
        for (int idx = bid * 256 + threadIdx.x; idx < BB * HH; idx += 64 * 256) {
            o2[BB * HH + idx]     = g_h1[idx];
            o2[3 * BB * HH + idx] = g_c1[idx];
        }
    } else {
        // ---------------- Group B: P1(k) + attn(k-2) ----------------
        const int bb = bid - 64;
        unsigned int tB = 0;
        for (int k = 0; k < TT + 2; k++) {
            if (k < TT) {
                // overwrite h0p[par k]: A P2(k-2) must be done
                if (k >= 2) wait_cnt(&g_cA, 64u * (unsigned)(k - 1));
                const half* a1h = (k & 1) ? g_h0h0 : g_h0h1;   // parity k-1
                const half* a1l = (k & 1) ? g_h0l0 : g_h0l1;
                half* wrh = (k & 1) ? g_h0h1 : g_h0h0;         // parity k
                half* wrl = (k & 1) ? g_h0l1 : g_h0l0;

                gates64_phase(dsm, bb,
                              a1h, a1l, g_Whh0h, g_Whh0l, HH,
                              nullptr, nullptr, nullptr, nullptr, 0,
                              nullptr, nullptr,
                              g_gin0 + (size_t)k * BB * FH,
                              g_h0, g_c0, wrh, wrl);
                tB += 64; group_sync(&g_barB, tB);
                bump_cnt(&g_cP1);
            }
            if (k >= 2) {
                const int v = k - 2;
                // h1 buf v%3 ready: P2(v) done
                wait_cnt(&g_cA, 64u * (unsigned)(v + 1));
                const half* rh = h1h[v % 3];
                const half* rl = h1l[v % 3];

                // P3: gamma = h1 @ attW^T + attb  (2 tiles)
                gemm32_phase(dsm, bb,
                             rh, rl, HH, g_attWh, g_attWl, HH, HH,
                             nullptr, nullptr, 0, nullptr, nullptr, 0, 0,
                             attb, g_gamma, HH, 0);
                gemm32_phase(dsm, bb + 64,
                             rh, rl, HH, g_attWh, g_attWl, HH, HH,
                             nullptr, nullptr, 0, nullptr, nullptr, 0, 0,
                             attb, g_gamma, HH, 0);
                tB += 64; group_sync(&g_barB, tB);

                // P4: attention (2 batches)
                attention_phase(dsm, contexts, g_gamma, g_ctxh, g_ctxl, bb);
                attention_phase(dsm, contexts, g_gamma, g_ctxh, g_ctxl, bb + 64);
                tB += 64; group_sync(&g_barB, tB);

                // P5: out[v] = tanh([ctx, h1] @ outW^T + outb)  (2 tiles)
                gemm32_phase(dsm, bb,
                             g_ctxh, g_ctxl, HH, g_outWh, g_outWl, 2 * HH, HH,
                             rh, rl, HH, g_outWh + HH, g_outWl + HH, 2 * HH, HH,
                             outb, out + (size_t)v * BB * HH, HH, 1);
                gemm32_phase(dsm, bb + 64,
                             g_ctxh, g_ctxl, HH, g_outWh, g_outWl, 2 * HH, HH,
                             rh, rl, HH, g_outWh + HH, g_outWl + HH, 2 * HH, HH,
                             outb, out + (size_t)v * BB * HH, HH, 1);
                bump_cnt(&g_cAT);
            }
        }
        // final h0 / c0 (layer-0 rows of hT/cT)
        float* o2 = out + (size_t)TT * BB * HH;
        for (int idx = bb * 256 + threadIdx.x; idx < BB * HH; idx += 64 * 256) {
            o2[idx]               = g_h0[idx];
            o2[2 * BB * HH + idx] = g_c0[idx];
        }
    }
}

// ---------------------------------------------------------------------------
// Launch: 3 kernels, single stream.
// ---------------------------------------------------------------------------
extern "C" void kernel_launch(void* const* d_in, const int* in_sizes, int n_in,
                              void* d_out, int out_size)
{
    (void)in_sizes; (void)n_in; (void)out_size;

    const int*   inputs   = (const int*)  d_in[0];
    const float* h0       = (const float*)d_in[1];
    const float* c0       = (const float*)d_in[2];
    const float* contexts = (const float*)d_in[3];
    const float* emb      = (const float*)d_in[4];
    const float* W_ih0    = (const float*)d_in[5];
    const float* W_hh0    = (const float*)d_in[6];
    const float* b_ih0    = (const float*)d_in[7];
    const float* b_hh0    = (const float*)d_in[8];
    const float* W_ih1    = (const float*)d_in[9];
    const float* W_hh1    = (const float*)d_in[10];
    const float* b_ih1    = (const float*)d_in[11];
    const float* b_hh1    = (const float*)d_in[12];
    const float* attW     = (const float*)d_in[13];
    const float* attb     = (const float*)d_in[14];
    const float* outW     = (const float*)d_in[15];
    const float* outb     = (const float*)d_in[16];
    float* out = (float*)d_out;

    constexpr int GSMEM = 4 * 12288;   // 49152
    static bool init_done = false;
    if (!init_done) {
        cudaFuncSetAttribute(persistent_kernel,
                             cudaFuncAttributeMaxDynamicSharedMemorySize, GSMEM);
        init_done = true;
    }

    prologue_kernel<<<1184, 256>>>(emb, W_ih0, W_hh0, W_ih1, W_hh1,
                                   attW, outW, h0, c0);
    {
        dim3 grid(FH / 32, (TT * BB) / 64);
        gin0_gemm_kernel<<<grid, 128>>>(inputs, b_ih0, b_hh0);
    }
    persistent_kernel<<<128, 256, GSMEM>>>(b_ih1, b_hh1, attb, outb,
                                           contexts, out);
}

// round 14
// speedup vs baseline: 1.0073x; 1.0073x over previous
#include <cuda_runtime.h>
#include <cuda_fp16.h>
#include <math.h>
#include <stdint.h>

// Problem dims (fixed by reference)
#define TT 128
#define BB 128
#define SS 128
#define HH 1024
#define EE 512
#define FH 4096   // 4*H
#define VV 32000

#define INV2048 4.8828125e-4f

// ---------------------------------------------------------------------------
// Scratch (device globals: allocation-free contract)
// ---------------------------------------------------------------------------
__device__ float g_gin0[(size_t)TT * BB * FH];
__device__ float g_h0[BB * HH];
__device__ float g_c0[BB * HH];
__device__ float g_h1[BB * HH];
__device__ float g_c1[BB * HH];
__device__ float g_gamma[BB * HH];

// fp16 split buffers: x = hi + lo/2048  (lo stored pre-scaled by 2048)
__device__ half g_embh [(size_t)VV * EE];
__device__ half g_embl [(size_t)VV * EE];
__device__ half g_Wih0h[(size_t)FH * EE];
__device__ half g_Wih0l[(size_t)FH * EE];
__device__ half g_Whh0h[(size_t)FH * HH];
__device__ half g_Whh0l[(size_t)FH * HH];
__device__ half g_Wih1h[(size_t)FH * HH];
__device__ half g_Wih1l[(size_t)FH * HH];
__device__ half g_Whh1h[(size_t)FH * HH];
__device__ half g_Whh1l[(size_t)FH * HH];
__device__ half g_attWh[(size_t)HH * HH];
__device__ half g_attWl[(size_t)HH * HH];
__device__ half g_outWh[(size_t)HH * 2 * HH];
__device__ half g_outWl[(size_t)HH * 2 * HH];

// h0 pairs: parity double-buffer (P1(k) writes parity k&1; initial in parity 1)
__device__ half g_h0h0[BB * HH];
__device__ half g_h0l0[BB * HH];
__device__ half g_h0h1[BB * HH];
__device__ half g_h0l1[BB * HH];
// h1 pairs: 3-buffer mod 3 (P2(t) writes t%3; initial state in buf 2)
__device__ half g_h1hA[BB * HH];
__device__ half g_h1lA[BB * HH];
__device__ half g_h1hB[BB * HH];
__device__ half g_h1lB[BB * HH];
__device__ half g_h1hC[BB * HH];
__device__ half g_h1lC[BB * HH];
__device__ half g_ctxh[BB * HH];
__device__ half g_ctxl[BB * HH];

__device__ unsigned int g_barA;   // group-A barrier counter
__device__ unsigned int g_barB;   // group-B barrier counter
__device__ unsigned int g_cP1;    // B progress: +1/block after P1(k)   -> 64(k+1)
__device__ unsigned int g_cA;     // A progress: +1/block after P2(t)   -> 64(t+1)
__device__ unsigned int g_cAT;    // B progress: +1/block after attn(v) -> 64(v+1)

__device__ __forceinline__ float sigmoidf_(float x) {
    return 1.0f / (1.0f + __expf(-x));
}

__device__ __forceinline__ void split16(float x, half* h, half* l) {
    const half hh = __float2half_rn(x);
    *h = hh;
    *l = __float2half_rn((x - __half2float(hh)) * 2048.0f);
}

__device__ __forceinline__ uint32_t smem_u32(const void* p) {
    uint32_t a;
    asm("{ .reg .u64 t; cvta.to.shared.u64 t, %1; cvt.u32.u64 %0, t; }"
        : "=r"(a) : "l"(p));
    return a;
}

__device__ __forceinline__ void ldm4(uint32_t* r, uint32_t a) {
    asm volatile("ldmatrix.sync.aligned.m8n8.x4.shared.b16 {%0,%1,%2,%3}, [%4];"
                 : "=r"(r[0]), "=r"(r[1]), "=r"(r[2]), "=r"(r[3]) : "r"(a));
}

__device__ __forceinline__ void ldm2(uint32_t* r, uint32_t a) {
    asm volatile("ldmatrix.sync.aligned.m8n8.x2.shared.b16 {%0,%1}, [%2];"
                 : "=r"(r[0]), "=r"(r[1]) : "r"(a));
}

__device__ __forceinline__ void mma_f16(float* d, const uint32_t* a, const uint32_t* b) {
    asm volatile(
        "mma.sync.aligned.m16n8k16.row.col.f32.f16.f16.f32 "
        "{%0,%1,%2,%3}, {%4,%5,%6,%7}, {%8,%9}, {%0,%1,%2,%3};\n"
        : "+f"(d[0]), "+f"(d[1]), "+f"(d[2]), "+f"(d[3])
        : "r"(a[0]), "r"(a[1]), "r"(a[2]), "r"(a[3]), "r"(b[0]), "r"(b[1]));
}

__device__ __forceinline__ void cp16(void* smem, const void* gmem) {   // L1 (static)
    asm volatile("cp.async.ca.shared.global [%0], [%1], 16;"
                 :: "r"(smem_u32(smem)), "l"(gmem));
}

__device__ __forceinline__ void cp16cg(void* smem, const void* gmem) { // L2-only (dynamic)
    asm volatile("cp.async.cg.shared.global [%0], [%1], 16;"
                 :: "r"(smem_u32(smem)), "l"(gmem));
}

// Group barrier (R10-proven).
__device__ __forceinline__ void group_sync(unsigned int* bar, unsigned int target) {
    __syncthreads();
    __threadfence();
    if (threadIdx.x == 0) {
        atomicAdd(bar, 1u);
        unsigned int v;
        do {
            asm volatile("ld.acquire.gpu.u32 %0, [%1];"
                         : "=r"(v) : "l"(bar) : "memory");
        } while (v < target);
    }
    __syncthreads();
}

__device__ __forceinline__ void wait_cnt(unsigned int* cnt, unsigned int target) {
    if (threadIdx.x == 0) {
        unsigned int v;
        do {
            asm volatile("ld.acquire.gpu.u32 %0, [%1];"
                         : "=r"(v) : "l"(cnt) : "memory");
        } while (v < target);
    }
    __syncthreads();
}

__device__ __forceinline__ void bump_cnt(unsigned int* cnt) {
    __syncthreads();
    __threadfence();
    if (threadIdx.x == 0) atomicAdd(cnt, 1u);
}

// Smem tile layout: rows of 16 halves (32 B); chunk c of row r at
// r*32 + ((c ^ ((r>>2)&1))<<4)  -> conflict-free stores + ldmatrix.
__device__ __forceinline__ uint32_t swz(int row, int c) {
    return (uint32_t)(row * 32 + ((c ^ ((row >> 2) & 1)) << 4));
}

// ---------------------------------------------------------------------------
// Prologue: split weights/emb, init state, reset counters.
// h0 initial -> parity 1; h1 initial -> buf C (index 2).
// ---------------------------------------------------------------------------
__global__ void prologue_kernel(
    const float* __restrict__ emb,
    const float* __restrict__ W_ih0, const float* __restrict__ W_hh0,
    const float* __restrict__ W_ih1, const float* __restrict__ W_hh1,
    const float* __restrict__ attW,  const float* __restrict__ outW,
    const float* __restrict__ h0,    const float* __restrict__ c0)
{
    if (blockIdx.x == 0 && threadIdx.x == 0) {
        g_barA = 0u; g_barB = 0u; g_cP1 = 0u; g_cA = 0u; g_cAT = 0u;
    }

    const long nE = (long)VV * EE;
    const long n0 = (long)FH * EE, n1 = (long)FH * HH;
    const long n4 = (long)HH * HH, n5 = (long)HH * 2 * HH;
    const long nS = BB * HH;
    const long total = nE + n0 + 3 * n1 + n4 + n5 + nS;
    for (long i = (long)blockIdx.x * blockDim.x + threadIdx.x; i < total;
         i += (long)gridDim.x * blockDim.x) {
        long j = i;
        if (j < nE) { split16(emb[j],   &g_embh[j],  &g_embl[j]);  continue; } j -= nE;
        if (j < n0) { split16(W_ih0[j], &g_Wih0h[j], &g_Wih0l[j]); continue; } j -= n0;
        if (j < n1) { split16(W_hh0[j], &g_Whh0h[j], &g_Whh0l[j]); continue; } j -= n1;
        if (j < n1) { split16(W_ih1[j], &g_Wih1h[j], &g_Wih1l[j]); continue; } j -= n1;
        if (j < n1) { split16(W_hh1[j], &g_Whh1h[j], &g_Whh1l[j]); continue; } j -= n1;
        if (j < n4) { split16(attW[j],  &g_attWh[j], &g_attWl[j]); continue; } j -= n4;
        if (j < n5) { split16(outW[j],  &g_outWh[j], &g_outWl[j]); continue; } j -= n5;
        const float a  = h0[j];
        const float b2 = h0[BB * HH + j];
        g_h0[j] = a;  g_h1[j] = b2;
        g_c0[j] = c0[j];  g_c1[j] = c0[BB * HH + j];
        split16(a,  &g_h0h1[j], &g_h0l1[j]);   // h0 initial -> parity 1
        split16(b2, &g_h1hC[j], &g_h1lC[j]);   // h1 initial -> buf 2
    }
}

// ---------------------------------------------------------------------------
// gin0 GEMM (unchanged, proven): emb[inputs]·W_ih0^T + biases.
// ---------------------------------------------------------------------------
__global__ __launch_bounds__(128)
void gin0_gemm_kernel(const int* __restrict__ gidx,
                      const float* __restrict__ bias1,
                      const float* __restrict__ bias2)
{
    constexpr int STRIDE = 6144;
    __shared__ __align__(16) char sm[4 * STRIDE];

    const int tid  = threadIdx.x;
    const int lane = tid & 31;
    const int warp = tid >> 5;
    const int wm = (warp >> 1) * 32;
    const int wn = (warp & 1) * 16;
    const int row0 = blockIdx.y * 64;
    const int col0 = blockIdx.x * 32;
    const uint32_t sbase = smem_u32(sm);

    uint32_t aoff[2];
#pragma unroll
    for (int mi = 0; mi < 2; mi++) {
        const int r = wm + mi * 16 + ((lane >> 3) & 1) * 8 + (lane & 7);
        aoff[mi] = swz(r, lane >> 4);
    }
    uint32_t boff;
    {
        const int m = lane >> 3;
        const int n = wn + (m >> 1) * 8 + (lane & 7);
        boff = swz(n, m & 1);
    }

    const int arow = tid >> 1, ac = tid & 1;
    const uint32_t asw = swz(arow, ac);
    const int bcomp = tid >> 6;
    const int bn = (tid & 63) >> 1, bc = tid & 1;
    const uint32_t bsw = swz(bn, bc) + (bcomp ? 1024u : 0u);

    float D1[2][2][4], D2[2][2][4];
#pragma unroll
    for (int mi = 0; mi < 2; mi++)
#pragma unroll
        for (int ni = 0; ni < 2; ni++)
#pragma unroll
            for (int q = 0; q < 4; q++) { D1[mi][ni][q] = 0.f; D2[mi][ni][q] = 0.f; }

#define G0LOAD(buf_, k0_)                                                        \
    do {                                                                         \
        const size_t ro = (size_t)gidx[row0 + arow] * EE;                        \
        cp16(sm + (buf_)*STRIDE + asw,        g_embh + ro + (k0_) + ac * 8);     \
        cp16(sm + (buf_)*STRIDE + 2048 + asw, g_embl + ro + (k0_) + ac * 8);     \
        {                                                                        \
            const half* wb = bcomp ? g_Wih0l : g_Wih0h;                          \
            cp16(sm + (buf_)*STRIDE + 4096 + bsw,                                \
                 wb + (size_t)(col0 + bn) * EE + (k0_) + bc * 8);                \
        }                                                                        \
    } while (0)

#define G0MMA(buf_)                                                              \
    do {                                                                         \
        const uint32_t st = sbase + (buf_)*STRIDE;                               \
        uint32_t bhv[4], blv[4];                                                 \
        ldm4(bhv, st + 4096 + boff);                                             \
        ldm4(blv, st + 5120 + boff);                                             \
        _Pragma("unroll")                                                        \
        for (int mi = 0; mi < 2; mi++) {                                         \
            uint32_t ah[4], al_[4];                                              \
            ldm4(ah,  st + aoff[mi]);                                            \
            ldm4(al_, st + 2048 + aoff[mi]);                                     \
            _Pragma("unroll")                                                    \
            for (int ni = 0; ni < 2; ni++) {                                     \
                mma_f16(D1[mi][ni], ah,  bhv + 2 * ni);                          \
                mma_f16(D2[mi][ni], ah,  blv + 2 * ni);                          \
                mma_f16(D2[mi][ni], al_, bhv + 2 * ni);                          \
            }                                                                    \
        }                                                                        \
    } while (0)

    const int niter = EE >> 4;
#pragma unroll
    for (int p = 0; p < 3; ++p) {
        G0LOAD(p, p << 4);
        asm volatile("cp.async.commit_group;");
    }
    for (int it0 = 0; it0 < niter; it0 += 4) {
#pragma unroll
        for (int sb = 0; sb < 4; sb++) {
            const int it = it0 + sb;
            const int nx = it + 3;
            constexpr int nlut[4] = {3, 0, 1, 2};
            if (nx < niter) G0LOAD(nlut[sb], nx << 4);
            asm volatile("cp.async.commit_group;");
            asm volatile("cp.async.wait_group 3;");
            __syncthreads();
            G0MMA(sb);
            __syncthreads();
        }
    }
#undef G0LOAD
#undef G0MMA

#pragma unroll
    for (int mi = 0; mi < 2; mi++) {
#pragma unroll
        for (int ni = 0; ni < 2; ni++) {
            const int c = col0 + wn + ni * 8 + 2 * (lane & 3);
#pragma unroll
            for (int hr = 0; hr < 2; hr++) {
                const int r = row0 + wm + mi * 16 + (lane >> 2) + 8 * hr;
                float v0 = D1[mi][ni][2*hr+0] + D2[mi][ni][2*hr+0] * INV2048
                           + bias1[c] + bias2[c];
                float v1 = D1[mi][ni][2*hr+1] + D2[mi][ni][2*hr+1] * INV2048
                           + bias1[c+1] + bias2[c+1];
                *reinterpret_cast<float2*>(&g_gin0[(size_t)r * FH + c]) =
                    make_float2(v0, v1);
            }
        }
    }
}

// ---------------------------------------------------------------------------
// Fused gates-GEMM + cell, BN=64 tiles (R12-proven internals).
// ---------------------------------------------------------------------------
__device__ void gates64_phase(char* dsm, int tileid,
    const half* __restrict__ A1h, const half* __restrict__ A1l,
    const half* __restrict__ W1h, const half* __restrict__ W1l, int K1,
    const half* __restrict__ A2h, const half* __restrict__ A2l,
    const half* __restrict__ W2h, const half* __restrict__ W2l, int K2,
    const float* __restrict__ bias1, const float* __restrict__ bias2,
    const float* __restrict__ gin,
    float* __restrict__ h, float* __restrict__ c,
    half* __restrict__ hph, half* __restrict__ hpl)
{
    constexpr int STRIDE = 12288;
    const int tid  = threadIdx.x;
    const int lane = tid & 31;
    const int warp = tid >> 5;
    const int wm   = warp * 16;
    const int j0   = tileid * 16;
    const uint32_t sbase = smem_u32(dsm);

    const int ar = wm + ((lane >> 3) & 1) * 8 + (lane & 7);
    const uint32_t aoff = swz(ar, lane >> 4);
    uint32_t boff[4];
#pragma unroll
    for (int p = 0; p < 4; p++) {
        const int m = lane >> 3;
        const int n = (2 * p + (m >> 1)) * 8 + (lane & 7);
        boff[p] = swz(n, m & 1);
    }

    const int arow = tid >> 1, ac = tid & 1;
    const uint32_t asw = swz(arow, ac);
    const int bcomp = tid >> 7;
    const int bn = (tid & 127) >> 1, bc = tid & 1;
    const int wrow = (bn >> 4) * HH + j0 + (bn & 15);
    const uint32_t bsw = swz(bn, bc) + (bcomp ? 2048u : 0u);

    float D1[8][4], D2[8][4];
#pragma unroll
    for (int ni = 0; ni < 8; ni++)
#pragma unroll
        for (int q = 0; q < 4; q++) { D1[ni][q] = 0.f; D2[ni][q] = 0.f; }

#define GLOAD(buf_, k0_)                                                          \
    do {                                                                          \
        cp16cg(dsm + (buf_)*STRIDE + asw,        Ah_ + (size_t)arow*K + (k0_) + ac*8); \
        cp16cg(dsm + (buf_)*STRIDE + 4096 + asw, Al_ + (size_t)arow*K + (k0_) + ac*8); \
        {                                                                         \
            const half* wb = bcomp ? Wl_ : Wh_;                                   \
            cp16(dsm + (buf_)*STRIDE + 8192 + bsw,                                \
                 wb + (size_t)wrow * K + (k0_) + bc * 8);                         \
        }                                                                         \
    } while (0)

#define GMMA(buf_)                                                               \
    do {                                                                         \
        const uint32_t st = sbase + (buf_)*STRIDE;                               \
        uint32_t ah[4], al_[4];                                                  \
        ldm4(ah,  st + aoff);                                                    \
        ldm4(al_, st + 4096 + aoff);                                             \
        _Pragma("unroll")                                                        \
        for (int p = 0; p < 4; p++) {                                            \
            uint32_t bhv[4], blv[4];                                             \
            ldm4(bhv, st + 8192  + boff[p]);                                     \
            ldm4(blv, st + 10240 + boff[p]);                                     \
            _Pragma("unroll")                                                    \
            for (int w2 = 0; w2 < 2; w2++) {                                     \
                const int ni = 2 * p + w2;                                       \
                mma_f16(D1[ni], ah,  bhv + 2 * w2);                              \
                mma_f16(D2[ni], ah,  blv + 2 * w2);                              \
                mma_f16(D2[ni], al_, bhv + 2 * w2);                              \
            }                                                                    \
        }                                                                        \
    } while (0)

    for (int s = 0; s < 2; ++s) {
        const half* Ah_ = s ? A2h : A1h;
        if (Ah_ == nullptr) continue;
        const half* Al_ = s ? A2l : A1l;
        const half* Wh_ = s ? W2h : W1h;
        const half* Wl_ = s ? W2l : W1l;
        const int K     = s ? K2 : K1;
        const int niter = K >> 4;

#pragma unroll
        for (int p = 0; p < 3; ++p) {
            GLOAD(p, p << 4);
            asm volatile("cp.async.commit_group;");
        }
        for (int it0 = 0; it0 < niter; it0 += 4) {
#pragma unroll
            for (int sb = 0; sb < 4; sb++) {
                const int it = it0 + sb;
                const int nx = it + 3;
                constexpr int nlut[4] = {3, 0, 1, 2};
                if (nx < niter) GLOAD(nlut[sb], nx << 4);
                asm volatile("cp.async.commit_group;");
                asm volatile("cp.async.wait_group 3;");
                __syncthreads();
                GMMA(sb);
                __syncthreads();
            }
        }
    }
#undef GLOAD
#undef GMMA

    const int jl2 = 2 * (lane & 3);
#pragma unroll
    for (int hf = 0; hf < 2; hf++) {
        const int r = wm + (lane >> 2) + 8 * hf;
#pragma unroll
        for (int o = 0; o < 2; o++) {
#pragma unroll
            for (int e = 0; e < 2; e++) {
                const int q  = 2 * hf + e;
                const int jg = j0 + 8 * o + jl2 + e;
                float gi = D1[0 + o][q] + D2[0 + o][q] * INV2048;
                float gf = D1[2 + o][q] + D2[2 + o][q] * INV2048;
                float gg = D1[4 + o][q] + D2[4 + o][q] * INV2048;
                float go = D1[6 + o][q] + D2[6 + o][q] * INV2048;
                if (bias1) {
                    gi += bias1[jg];            gf += bias1[HH + jg];
                    gg += bias1[2 * HH + jg];   go += bias1[3 * HH + jg];
                }
                if (bias2) {
                    gi += bias2[jg];            gf += bias2[HH + jg];
                    gg += bias2[2 * HH + jg];   go += bias2[3 * HH + jg];
                }
                if (gin) {
                    const float* gr = gin + (size_t)r * FH;
                    gi += gr[jg];          gf += gr[HH + jg];
                    gg += gr[2 * HH + jg]; go += gr[3 * HH + jg];
                }
                const int idx = r * HH + jg;
                const float cn = sigmoidf_(gf) * c[idx] + sigmoidf_(gi) * tanhf(gg);
                const float hn = sigmoidf_(go) * tanhf(cn);
                c[idx] = cn;
                h[idx] = hn;
                split16(hn, &hph[idx], &hpl[idx]);
            }
        }
    }
}

// ---------------------------------------------------------------------------
// 32x32-tile GEMM (R11/12-proven internals).
// ---------------------------------------------------------------------------
__device__ void gemm32_phase(char* dsm, int tile,
    const half* __restrict__ A1h, const half* __restrict__ A1l, int lda1,
    const half* __restrict__ B1h, const half* __restrict__ B1l, int ldb1, int K1,
    const half* __restrict__ A2h, const half* __restrict__ A2l, int lda2,
    const half* __restrict__ B2h, const half* __restrict__ B2l, int ldb2, int K2,
    const float* __restrict__ bias,
    float* __restrict__ C, int ldc, int act)
{
    constexpr int STRIDE = 4096;
    const int tid  = threadIdx.x;
    const int lane = tid & 31;
    const int warp = tid >> 5;
    const int wm = (warp >> 2) * 16;
    const int wn = (warp & 3) * 8;
    const int row0 = (tile >> 5) * 32;
    const int col0 = (tile & 31) * 32;
    const uint32_t sbase = smem_u32(dsm);

    const int ar = wm + ((lane >> 3) & 1) * 8 + (lane & 7);
    const uint32_t aoff = swz(ar, lane >> 4);
    uint32_t boff;
    {
        const int m = (lane & 15) >> 3;
        const int n = wn + (lane & 7);
        boff = swz(n, m);
    }

    const int reg4 = tid >> 6;
    const int lrow = (tid & 63) >> 1, lc = tid & 1;
    const uint32_t lsw = swz(lrow, lc) + (uint32_t)reg4 * 1024u;

    float D1[4] = {0.f, 0.f, 0.f, 0.f};
    float D2[4] = {0.f, 0.f, 0.f, 0.f};

#define LT32(buf_, k0_)                                                           \
    do {                                                                          \
        if (reg4 < 2) {                                                           \
            const half* ab = reg4 ? Al_ : Ah_;                                    \
            cp16cg(dsm + (buf_)*STRIDE + lsw,                                     \
                   ab + (size_t)(row0 + lrow) * lda + (k0_) + lc * 8);            \
        } else {                                                                  \
            const half* bb = (reg4 == 3) ? Bl_ : Bh_;                             \
            cp16(dsm + (buf_)*STRIDE + lsw,                                       \
                 bb + (size_t)(col0 + lrow) * ldb + (k0_) + lc * 8);              \
        }                                                                         \
    } while (0)

#define MS32(buf_)                                                                \
    do {                                                                          \
        const uint32_t st = sbase + (buf_)*STRIDE;                                \
        uint32_t ah[4], al_[4], bh[2], bl[2];                                     \
        ldm4(ah,  st + aoff);                                                     \
        ldm4(al_, st + 1024 + aoff);                                              \
        ldm2(bh,  st + 2048 + boff);                                              \
        ldm2(bl,  st + 3072 + boff);                                              \
        mma_f16(D1, ah,  bh);                                                     \
        mma_f16(D2, ah,  bl);                                                     \
        mma_f16(D2, al_, bh);                                                     \
    } while (0)

    for (int s = 0; s < 2; ++s) {
        const half* Ah_ = s ? A2h : A1h;
        if (Ah_ == nullptr) continue;
        const half* Al_ = s ? A2l : A1l;
        const half* Bh_ = s ? B2h : B1h;
        const half* Bl_ = s ? B2l : B1l;
        const int lda = s ? lda2 : lda1;
        const int ldb = s ? ldb2 : ldb1;
        const int K   = s ? K2 : K1;
        const int niter = K >> 4;

#pragma unroll
        for (int p = 0; p < 3; ++p) {
            LT32(p, p << 4);
            asm volatile("cp.async.commit_group;");
        }
        for (int it0 = 0; it0 < niter; it0 += 4) {
#pragma unroll
            for (int sb = 0; sb < 4; sb++) {
                const int it = it0 + sb;
                const int nx = it + 3;
                constexpr int nlut[4] = {3, 0, 1, 2};
                if (nx < niter) LT32(nlut[sb], nx << 4);
                asm volatile("cp.async.commit_group;");
                asm volatile("cp.async.wait_group 3;");
                __syncthreads();
                MS32(sb);
                __syncthreads();
            }
        }
    }
#undef LT32
#undef MS32

    const int cc = col0 + wn + 2 * (lane & 3);
#pragma unroll
    for (int hf = 0; hf < 2; hf++) {
        const int r = row0 + wm + (lane >> 2) + 8 * hf;
        float v0 = D1[2*hf+0] + D2[2*hf+0] * INV2048 + bias[cc];
        float v1 = D1[2*hf+1] + D2[2*hf+1] * INV2048 + bias[cc+1];
        if (act == 1) { v0 = tanhf(v0); v1 = tanhf(v1); }
        *reinterpret_cast<float2*>(&C[(size_t)r * (size_t)ldc + cc]) =
            make_float2(v0, v1);
    }
}

// ---------------------------------------------------------------------------
// Attention phase (R11/12-proven internals).
// ---------------------------------------------------------------------------
__device__ void attention_phase(char* dsmc,
                                const float* __restrict__ contexts,
                                const float* __restrict__ gamma,
                                half* __restrict__ ctxh,
                                half* __restrict__ ctxl, int b)
{
    float* sg     = reinterpret_cast<float*>(dsmc);
    float* sw     = sg + HH;
    float* red    = sw + SS;
    float* s_stat = red + 8;

    const int tid  = threadIdx.x;
    const int lane = tid & 31;
    const int warp = tid >> 5;
    const float* cb = contexts + (size_t)b * SS * HH;

    for (int j = tid; j < HH; j += 256) sg[j] = __ldcg(&gamma[(size_t)b * HH + j]);
    __syncthreads();

    for (int s = warp; s < SS; s += 8) {
        const float* cr = cb + (size_t)s * HH;
        float sum = 0.0f;
#pragma unroll 4
        for (int j = lane * 4; j < HH; j += 128) {
            float4 v = *reinterpret_cast<const float4*>(&cr[j]);
            sum = fmaf(v.x, sg[j], sum);
            sum = fmaf(v.y, sg[j + 1], sum);
            sum = fmaf(v.z, sg[j + 2], sum);
            sum = fmaf(v.w, sg[j + 3], sum);
        }
#pragma unroll
        for (int off = 16; off; off >>= 1)
            sum += __shfl_xor_sync(0xffffffffu, sum, off);
        if (lane == 0) sw[s] = sum;
    }
    __syncthreads();

    const float v = (tid < SS) ? sw[tid] : -3.4e38f;
    float m = v;
#pragma unroll
    for (int off = 16; off; off >>= 1)
        m = fmaxf(m, __shfl_xor_sync(0xffffffffu, m, off));
    if (lane == 0) red[warp] = m;
    __syncthreads();
    if (tid == 0) {
        float mm = red[0];
        for (int w2 = 1; w2 < 8; w2++) mm = fmaxf(mm, red[w2]);
        *s_stat = mm;
    }
    __syncthreads();
    const float bm = *s_stat;
    const float e = (tid < SS) ? __expf(v - bm) : 0.0f;
    float s2 = e;
#pragma unroll
    for (int off = 16; off; off >>= 1)
        s2 += __shfl_xor_sync(0xffffffffu, s2, off);
    if (lane == 0) red[warp] = s2;
    __syncthreads();
    if (tid == 0) {
        float t = 0.0f;
        for (int w2 = 0; w2 < 8; w2++) t += red[w2];
        *s_stat = 1.0f / t;
    }
    __syncthreads();
    if (tid < SS) sw[tid] = e * (*s_stat);
    __syncthreads();

    float acc[4] = {0.0f, 0.0f, 0.0f, 0.0f};
    for (int s = 0; s < SS; s++) {
        const float w = sw[s];
        const float* cr = cb + (size_t)s * HH;
#pragma unroll
        for (int q = 0; q < 4; q++)
            acc[q] = fmaf(w, cr[tid + q * 256], acc[q]);
    }
#pragma unroll
    for (int q = 0; q < 4; q++) {
        const int idx = b * HH + tid + q * 256;
        split16(acc[q], &ctxh[idx], &ctxl[idx]);
    }
}

// ---------------------------------------------------------------------------
// Persistent kernel: pipelined two-group schedule.
//  Cycle k:  B (blocks 64-127): P1(k) [k<TT]  +  attn(k-2) [k>=2]
//            A (blocks 0-63):   P2(k-1)       [1<=k<=TT]
//  h0 pairs: parity (P1(k) -> k&1).  h1 pairs: mod-3 (P2(t) -> t%3).
//  Counters: cP1 (after P1), cA (after P2), cAT (after attn P5).
// ---------------------------------------------------------------------------
__global__ __launch_bounds__(256)
void persistent_kernel(const float* __restrict__ b_ih1,
                       const float* __restrict__ b_hh1,
                       const float* __restrict__ attb,
                       const float* __restrict__ outb,
                       const float* __restrict__ contexts,
                       float* __restrict__ out)
{
    extern __shared__ __align__(16) char dsm[];
    const int bid = blockIdx.x;

    half* const h1h[3] = { g_h1hA, g_h1hB, g_h1hC };
    half* const h1l[3] = { g_h1lA, g_h1lB, g_h1lC };

    if (bid < 64) {
        // ---------------- Group A: P2(t) for t = 0..TT-1 ----------------
        unsigned int tA = 0;
        for (int t = 0; t < TT; t++) {
            // h0p[par t] ready: P1(t) done
            wait_cnt(&g_cP1, 64u * (unsigned)(t + 1));
            // overwrite h1 buf t%3: attn(t-3) must be done
            if (t >= 3) wait_cnt(&g_cAT, 64u * (unsigned)(t - 2));

            const half* a1h = (t & 1) ? g_h0h1 : g_h0h0;
            const half* a1l = (t & 1) ? g_h0l1 : g_h0l0;
            const int rb = (t + 2) % 3;     // (t-1) mod 3
            const int wb = t % 3;

            gates64_phase(dsm, bid,
                          a1h, a1l, g_Wih1h, g_Wih1l, HH,
                          h1h[rb], h1l[rb], g_Whh1h, g_Whh1l, HH,
                          b_ih1, b_hh1,
                          nullptr,
                          g_h1, g_c1, h1h[wb], h1l[wb]);
            tA += 64; group_sync(&g_barA, tA);
            bump_cnt(&g_cA);
        }
        // final h1 / c1 (layer-1 rows of hT/cT)
        float* o2 = out + (size_t)TT * BB * HH;
        for (int idx = bid * 256 + threadIdx.x; idx < BB * HH; idx += 64 * 256) {
            o2[BB * HH + idx]     = g_h1[idx];
            o2[3 * BB * HH + idx] = g_c1[idx];
        }
    } else {
        // ---------------- Group B: P1(k) + attn(k-2) ----------------
        const int bb = bid - 64;
        unsigned int tB = 0;
        for (int k = 0; k < TT + 2; k++) {
            if (k < TT) {
                // overwrite h0p[par k]: A P2(k-2) must be done
                if (k >= 2) wait_cnt(&g_cA, 64u * (unsigned)(k - 1));
                const half* a1h = (k & 1) ? g_h0h0 : g_h0h1;   // parity k-1
                const half* a1l = (k & 1) ? g_h0l0 : g_h0l1;
                half* wrh = (k & 1) ? g_h0h1 : g_h0h0;         // parity k
                half* wrl = (k & 1) ? g_h0l1 : g_h0l0;

                gates64_phase(dsm, bb,
                              a1h, a1l, g_Whh0h, g_Whh0l, HH,
                              nullptr, nullptr, nullptr, nullptr, 0,
                              nullptr, nullptr,
                              g_gin0 + (size_t)k * BB * FH,
                              g_h0, g_c0, wrh, wrl);
                tB += 64; group_sync(&g_barB, tB);
                bump_cnt(&g_cP1);
            }
            if (k >= 2) {
                const int v = k - 2;
                // h1 buf v%3 ready: P2(v) done
                wait_cnt(&g_cA, 64u * (unsigned)(v + 1));
                const half* rh = h1h[v % 3];
                const half* rl = h1l[v % 3];

                // P3: gamma = h1 @ attW^T + attb  (2 tiles)
                gemm32_phase(dsm, bb,
                             rh, rl, HH, g_attWh, g_attWl, HH, HH,
                             nullptr, nullptr, 0, nullptr, nullptr, 0, 0,
                             attb, g_gamma, HH, 0);
                gemm32_phase(dsm, bb + 64,
                             rh, rl, HH, g_attWh, g_attWl, HH, HH,
                             nullptr, nullptr, 0, nullptr, nullptr, 0, 0,
                             attb, g_gamma, HH, 0);
                tB += 64; group_sync(&g_barB, tB);

                // P4: attention (2 batches)
                attention_phase(dsm, contexts, g_gamma, g_ctxh, g_ctxl, bb);
                attention_phase(dsm, contexts, g_gamma, g_ctxh, g_ctxl, bb + 64);
                tB += 64; group_sync(&g_barB, tB);

                // P5: out[v] = tanh([ctx, h1] @ outW^T + outb)  (2 tiles)
                gemm32_phase(dsm, bb,
                             g_ctxh, g_ctxl, HH, g_outWh, g_outWl, 2 * HH, HH,
                             rh, rl, HH, g_outWh + HH, g_outWl + HH, 2 * HH, HH,
                             outb, out + (size_t)v * BB * HH, HH, 1);
                gemm32_phase(dsm, bb + 64,
                             g_ctxh, g_ctxl, HH, g_outWh, g_outWl, 2 * HH, HH,
                             rh, rl, HH, g_outWh + HH, g_outWl + HH, 2 * HH, HH,
                             outb, out + (size_t)v * BB * HH, HH, 1);
                bump_cnt(&g_cAT);
            }
        }
        // final h0 / c0 (layer-0 rows of hT/cT)
        float* o2 = out + (size_t)TT * BB * HH;
        for (int idx = bb * 256 + threadIdx.x; idx < BB * HH; idx += 64 * 256) {
            o2[idx]               = g_h0[idx];
            o2[2 * BB * HH + idx] = g_c0[idx];
        }
    }
}

// ---------------------------------------------------------------------------
// Launch: 3 kernels, single stream.
// ---------------------------------------------------------------------------
extern "C" void kernel_launch(void* const* d_in, const int* in_sizes, int n_in,
                              void* d_out, int out_size)
{
    (void)in_sizes; (void)n_in; (void)out_size;

    const int*   inputs   = (const int*)  d_in[0];
    const float* h0       = (const float*)d_in[1];
    const float* c0       = (const float*)d_in[2];
    const float* contexts = (const float*)d_in[3];
    const float* emb      = (const float*)d_in[4];
    const float* W_ih0    = (const float*)d_in[5];
    const float* W_hh0    = (const float*)d_in[6];
    const float* b_ih0    = (const float*)d_in[7];
    const float* b_hh0    = (const float*)d_in[8];
    const float* W_ih1    = (const float*)d_in[9];
    const float* W_hh1    = (const float*)d_in[10];
    const float* b_ih1    = (const float*)d_in[11];
    const float* b_hh1    = (const float*)d_in[12];
    const float* attW     = (const float*)d_in[13];
    const float* attb     = (const float*)d_in[14];
    const float* outW     = (const float*)d_in[15];
    const float* outb     = (const float*)d_in[16];
    float* out = (float*)d_out;

    constexpr int GSMEM = 4 * 12288;   // 49152
    static bool init_done = false;
    if (!init_done) {
        cudaFuncSetAttribute(persistent_kernel,
                             cudaFuncAttributeMaxDynamicSharedMemorySize, GSMEM);
        init_done = true;
    }

    prologue_kernel<<<1184, 256>>>(emb, W_ih0, W_hh0, W_ih1, W_hh1,
                                   attW, outW, h0, c0);
    {
        dim3 grid(FH / 32, (TT * BB) / 64);
        gin0_gemm_kernel<<<grid, 128>>>(inputs, b_ih0, b_hh0);
    }
    persistent_kernel<<<128, 256, GSMEM>>>(b_ih1, b_hh1, attb, outb,
                                           contexts, out);
}

// round 16
// speedup vs baseline: 1.5030x; 1.4921x over previous
#include <cuda_runtime.h>
#include <cuda_fp16.h>
#include <math.h>
#include <stdint.h>

#define TT 128
#define BB 128
#define SS 128
#define HH 1024
#define EE 512
#define FH 4096
#define VV 32000
#define INV2048 4.8828125e-4f

__device__ float g_gin0[(size_t)TT * BB * FH];
__device__ float g_h0[BB * HH];
__device__ float g_c0[BB * HH];
__device__ float g_h1[BB * HH];
__device__ float g_c1[BB * HH];
__device__ float g_gamma[BB * HH];

__device__ half g_embh [(size_t)VV * EE];
__device__ half g_embl [(size_t)VV * EE];
__device__ half g_Wih0h[(size_t)FH * EE];
__device__ half g_Wih0l[(size_t)FH * EE];
__device__ half g_Whh0h[(size_t)FH * HH];
__device__ half g_Whh0l[(size_t)FH * HH];
__device__ half g_Wih1h[(size_t)FH * HH];
__device__ half g_Wih1l[(size_t)FH * HH];
__device__ half g_Whh1h[(size_t)FH * HH];
__device__ half g_Whh1l[(size_t)FH * HH];
__device__ half g_attWh[(size_t)HH * HH];
__device__ half g_attWl[(size_t)HH * HH];
__device__ half g_outWh[(size_t)HH * 2 * HH];
__device__ half g_outWl[(size_t)HH * 2 * HH];
__device__ half g_h0p_h[BB * HH];
__device__ half g_h0p_l[BB * HH];
__device__ half g_h1hA[BB * HH];
__device__ half g_h1lA[BB * HH];
__device__ half g_h1hB[BB * HH];
__device__ half g_h1lB[BB * HH];
__device__ half g_h1hC[BB * HH];
__device__ half g_h1lC[BB * HH];
__device__ half g_ctxh[BB * HH];
__device__ half g_ctxl[BB * HH];

__device__ unsigned int g_barA;
__device__ unsigned int g_barB;
__device__ unsigned int g_cA;
__device__ unsigned int g_cB;

__device__ __forceinline__ float sigmoidf_(float x) {
    return 1.0f / (1.0f + __expf(-x));
}

__device__ __forceinline__ void split16(float x, half* h, half* l) {
    const half hh = __float2half_rn(x);
    *h = hh;
    *l = __float2half_rn((x - __half2float(hh)) * 2048.0f);
}

__device__ __forceinline__ uint32_t smem_u32(const void* p) {
    uint32_t a;
    asm("{ .reg .u64 t; cvta.to.shared.u64 t, %1; cvt.u32.u64 %0, t; }"
        : "=r"(a) : "l"(p));
    return a;
}

__device__ __forceinline__ void ldm4(uint32_t* r, uint32_t a) {
    asm volatile("ldmatrix.sync.aligned.m8n8.x4.shared.b16 {%0,%1,%2,%3}, [%4];"
                 : "=r"(r[0]), "=r"(r[1]), "=r"(r[2]), "=r"(r[3]) : "r"(a));
}

__device__ __forceinline__ void mma_f16(float* d, const uint32_t* a, const uint32_t* b) {
    asm volatile(
        "mma.sync.aligned.m16n8k16.row.col.f32.f16.f16.f32 "
        "{%0,%1,%2,%3}, {%4,%5,%6,%7}, {%8,%9}, {%0,%1,%2,%3};\n"
        : "+f"(d[0]), "+f"(d[1]), "+f"(d[2]), "+f"(d[3])
        : "r"(a[0]), "r"(a[1]), "r"(a[2]), "r"(a[3]), "r"(b[0]), "r"(b[1]));
}

__device__ __forceinline__ void cp16(void* smem, const void* gmem) {
    asm volatile("cp.async.ca.shared.global [%0], [%1], 16;"
                 :: "r"(smem_u32(smem)), "l"(gmem));
}

__device__ __forceinline__ void cp16cg(void* smem, const void* gmem) {
    asm volatile("cp.async.cg.shared.global [%0], [%1], 16;"
                 :: "r"(smem_u32(smem)), "l"(gmem));
}

__device__ __forceinline__ void group_sync(unsigned int* bar, unsigned int target) {
    __syncthreads();
    __threadfence();
    if (threadIdx.x == 0) {
        atomicAdd(bar, 1u);
        unsigned int v;
        do {
            asm volatile("ld.acquire.gpu.u32 %0, [%1];"
                         : "=r"(v) : "l"(bar) : "memory");
        } while (v < target);
    }
    __syncthreads();
}

__device__ __forceinline__ void wait_cnt(unsigned int* cnt, unsigned int target) {
    if (threadIdx.x == 0) {
        unsigned int v;
        do {
            asm volatile("ld.acquire.gpu.u32 %0, [%1];"
                         : "=r"(v) : "l"(cnt) : "memory");
        } while (v < target);
    }
    __syncthreads();
}

__device__ __forceinline__ void bump_cnt(unsigned int* cnt) {
    __syncthreads();
    __threadfence();
    if (threadIdx.x == 0) atomicAdd(cnt, 1u);
}

__device__ __forceinline__ uint32_t swz(int row, int c) {
    return (uint32_t)(row * 32 + ((c ^ ((row >> 2) & 1)) << 4));
}

// ---------------------------------------------------------------------------
// Prologue: split weights/emb, init state, reset counters.
// ---------------------------------------------------------------------------
__global__ void prologue_kernel(
    const float* __restrict__ emb,
    const float* __restrict__ W_ih0, const float* __restrict__ W_hh0,
    const float* __restrict__ W_ih1, const float* __restrict__ W_hh1,
    const float* __restrict__ attW,  const float* __restrict__ outW,
    const float* __restrict__ h0,    const float* __restrict__ c0)
{
    if (blockIdx.x == 0 && threadIdx.x == 0) {
        g_barA = 0u; g_barB = 0u; g_cA = 0u; g_cB = 0u;
    }
    const long nE = (long)VV * EE;
    const long n0 = (long)FH * EE, n1 = (long)FH * HH;
    const long n4 = (long)HH * HH, n5 = (long)HH * 2 * HH;
    const long nS = BB * HH;
    const long total = nE + n0 + 3 * n1 + n4 + n5 + nS;
    for (long i = (long)blockIdx.x * blockDim.x + threadIdx.x; i < total;
         i += (long)gridDim.x * blockDim.x) {
        long j = i;
        if (j < nE) { split16(emb[j],   &g_embh[j],  &g_embl[j]);  continue; } j -= nE;
        if (j < n0) { split16(W_ih0[j], &g_Wih0h[j], &g_Wih0l[j]); continue; } j -= n0;
        if (j < n1) { split16(W_hh0[j], &g_Whh0h[j], &g_Whh0l[j]); continue; } j -= n1;
        if (j < n1) { split16(W_ih1[j], &g_Wih1h[j], &g_Wih1l[j]); continue; } j -= n1;
        if (j < n1) { split16(W_hh1[j], &g_Whh1h[j], &g_Whh1l[j]); continue; } j -= n1;
        if (j < n4) { split16(attW[j],  &g_attWh[j], &g_attWl[j]); continue; } j -= n4;
        if (j < n5) { split16(outW[j],  &g_outWh[j], &g_outWl[j]); continue; } j -= n5;
        const float a  = h0[j];
        const float b2 = h0[BB * HH + j];
        g_h0[j] = a;  g_h1[j] = b2;
        g_c0[j] = c0[j];  g_c1[j] = c0[BB * HH + j];
        split16(a,  &g_h0p_h[j], &g_h0p_l[j]);
        split16(b2, &g_h1hC[j],  &g_h1lC[j]);    // initial h1 -> buf 2
    }
}

// ---------------------------------------------------------------------------
// gin0 GEMM (R11-proven): emb[inputs]·W_ih0^T + biases.
// ---------------------------------------------------------------------------
__global__ __launch_bounds__(128)
void gin0_gemm_kernel(const int* __restrict__ gidx,
                      const float* __restrict__ bias1,
                      const float* __restrict__ bias2)
{
    constexpr int STRIDE = 6144;
    __shared__ __align__(16) char sm[4 * STRIDE];

    const int tid  = threadIdx.x;
    const int lane = tid & 31;
    const int warp = tid >> 5;
    const int wm = (warp >> 1) * 32;
    const int wn = (warp & 1) * 16;
    const int row0 = blockIdx.y * 64;
    const int col0 = blockIdx.x * 32;
    const uint32_t sbase = smem_u32(sm);

    uint32_t aoff[2];
#pragma unroll
    for (int mi = 0; mi < 2; mi++) {
        const int r = wm + mi * 16 + ((lane >> 3) & 1) * 8 + (lane & 7);
        aoff[mi] = swz(r, lane >> 4);
    }
    uint32_t boff;
    {
        const int m = lane >> 3;
        const int n = wn + (m >> 1) * 8 + (lane & 7);
        boff = swz(n, m & 1);
    }

    const int arow = tid >> 1, ac = tid & 1;
    const uint32_t asw = swz(arow, ac);
    const int bcomp = tid >> 6;
    const int bn = (tid & 63) >> 1, bc = tid & 1;
    const uint32_t bsw = swz(bn, bc) + (bcomp ? 1024u : 0u);

    float D1[2][2][4], D2[2][2][4];
#pragma unroll
    for (int mi = 0; mi < 2; mi++)
#pragma unroll
        for (int ni = 0; ni < 2; ni++)
#pragma unroll
            for (int q = 0; q < 4; q++) { D1[mi][ni][q] = 0.f; D2[mi][ni][q] = 0.f; }

#define G0LOAD(buf_, k0_)                                                        \
    do {                                                                         \
        const size_t ro = (size_t)gidx[row0 + arow] * EE;                        \
        cp16(sm + (buf_)*STRIDE + asw,        g_embh + ro + (k0_) + ac * 8);     \
        cp16(sm + (buf_)*STRIDE + 2048 + asw, g_embl + ro + (k0_) + ac * 8);     \
        {                                                                        \
            const half* wb = bcomp ? g_Wih0l : g_Wih0h;                          \
            cp16(sm + (buf_)*STRIDE + 4096 + bsw,                                \
                 wb + (size_t)(col0 + bn) * EE + (k0_) + bc * 8);                \
        }                                                                        \
    } while (0)

#define G0MMA(buf_)                                                              \
    do {                                                                         \
        const uint32_t st = sbase + (buf_)*STRIDE;                               \
        uint32_t bhv[4], blv[4];                                                 \
        ldm4(bhv, st + 4096 + boff);                                             \
        ldm4(blv, st + 5120 + boff);                                             \
        _Pragma("unroll")                                                        \
        for (int mi = 0; mi < 2; mi++) {                                         \
            uint32_t ah[4], al_[4];                                              \
            ldm4(ah,  st + aoff[mi]);                                            \
            ldm4(al_, st + 2048 + aoff[mi]);                                     \
            _Pragma("unroll")                                                    \
            for (int ni = 0; ni < 2; ni++) {                                     \
                mma_f16(D1[mi][ni], ah,  bhv + 2 * ni);                          \
                mma_f16(D2[mi][ni], ah,  blv + 2 * ni);                          \
                mma_f16(D2[mi][ni], al_, bhv + 2 * ni);                          \
            }                                                                    \
        }                                                                        \
    } while (0)

    const int niter = EE >> 4;
#pragma unroll
    for (int p = 0; p < 3; ++p) {
        G0LOAD(p, p << 4);
        asm volatile("cp.async.commit_group;");
    }
    for (int it0 = 0; it0 < niter; it0 += 4) {
#pragma unroll
        for (int sb = 0; sb < 4; sb++) {
            const int it = it0 + sb;
            const int nx = it + 3;
            constexpr int nlut[4] = {3, 0, 1, 2};
            if (nx < niter) G0LOAD(nlut[sb], nx << 4);
            asm volatile("cp.async.commit_group;");
            asm volatile("cp.async.wait_group 3;");
            __syncthreads();
            G0MMA(sb);
            __syncthreads();
        }
    }
#undef G0LOAD
#undef G0MMA

#pragma unroll
    for (int mi = 0; mi < 2; mi++) {
#pragma unroll
        for (int ni = 0; ni < 2; ni++) {
            const int c = col0 + wn + ni * 8 + 2 * (lane & 3);
#pragma unroll
            for (int hr = 0; hr < 2; hr++) {
                const int r = row0 + wm + mi * 16 + (lane >> 2) + 8 * hr;
                float v0 = D1[mi][ni][2*hr+0] + D2[mi][ni][2*hr+0] * INV2048
                           + bias1[c] + bias2[c];
                float v1 = D1[mi][ni][2*hr+1] + D2[mi][ni][2*hr+1] * INV2048
                           + bias1[c+1] + bias2[c+1];
                *reinterpret_cast<float2*>(&g_gin0[(size_t)r * FH + c]) =
                    make_float2(v0, v1);
            }
        }
    }
}

// ---------------------------------------------------------------------------
// Fused gates-GEMM + cell, 128x64 tile (R12-proven, byte-identical).
// ---------------------------------------------------------------------------
__device__ void gates64_phase(char* dsm, int tileid,
    const half* __restrict__ A1h, const half* __restrict__ A1l,
    const half* __restrict__ W1h, const half* __restrict__ W1l, int K1,
    const half* __restrict__ A2h, const half* __restrict__ A2l,
    const half* __restrict__ W2h, const half* __restrict__ W2l, int K2,
    const float* __restrict__ bias1, const float* __restrict__ bias2,
    const float* __restrict__ gin,
    float* __restrict__ h, float* __restrict__ c,
    half* __restrict__ hph, half* __restrict__ hpl)
{
    constexpr int STRIDE = 12288;
    const int tid  = threadIdx.x;
    const int lane = tid & 31;
    const int warp = tid >> 5;
    const int wm   = warp * 16;
    const int j0   = tileid * 16;
    const uint32_t sbase = smem_u32(dsm);

    const int ar = wm + ((lane >> 3) & 1) * 8 + (lane & 7);
    const uint32_t aoff = swz(ar, lane >> 4);
    uint32_t boff[4];
#pragma unroll
    for (int p = 0; p < 4; p++) {
        const int m = lane >> 3;
        const int n = (2 * p + (m >> 1)) * 8 + (lane & 7);
        boff[p] = swz(n, m & 1);
    }

    const int arow = tid >> 1, ac = tid & 1;
    const uint32_t asw = swz(arow, ac);
    const int bcomp = tid >> 7;
    const int bn = (tid & 127) >> 1, bc = tid & 1;
    const int wrow = (bn >> 4) * HH + j0 + (bn & 15);
    const uint32_t bsw = swz(bn, bc) + (bcomp ? 2048u : 0u);

    float D1[8][4], D2[8][4];
#pragma unroll
    for (int ni = 0; ni < 8; ni++)
#pragma unroll
        for (int q = 0; q < 4; q++) { D1[ni][q] = 0.f; D2[ni][q] = 0.f; }

#define GLOAD(buf_, k0_)                                                          \
    do {                                                                          \
        cp16cg(dsm + (buf_)*STRIDE + asw,        Ah_ + (size_t)arow*K + (k0_) + ac*8); \
        cp16cg(dsm + (buf_)*STRIDE + 4096 + asw, Al_ + (size_t)arow*K + (k0_) + ac*8); \
        {                                                                         \
            const half* wb = bcomp ? Wl_ : Wh_;                                   \
            cp16(dsm + (buf_)*STRIDE + 8192 + bsw,                                \
                 wb + (size_t)wrow * K + (k0_) + bc * 8);                         \
        }                                                                         \
    } while (0)

#define GMMA(buf_)                                                               \
    do {                                                                         \
        const uint32_t st = sbase + (buf_)*STRIDE;                               \
        uint32_t ah[4], al_[4];                                                  \
        ldm4(ah,  st + aoff);                                                    \
        ldm4(al_, st + 4096 + aoff);                                             \
        _Pragma("unroll")                                                        \
        for (int p = 0; p < 4; p++) {                                            \
            uint32_t bhv[4], blv[4];                                             \
            ldm4(bhv, st + 8192  + boff[p]);                                     \
            ldm4(blv, st + 10240 + boff[p]);                                     \
            _Pragma("unroll")                                                    \
            for (int w2 = 0; w2 < 2; w2++) {                                     \
                const int ni = 2 * p + w2;                                       \
                mma_f16(D1[ni], ah,  bhv + 2 * w2);                              \
                mma_f16(D2[ni], ah,  blv + 2 * w2);                              \
                mma_f16(D2[ni], al_, bhv + 2 * w2);                              \
            }                                                                    \
        }                                                                        \
    } while (0)

    for (int s = 0; s < 2; ++s) {
        const half* Ah_ = s ? A2h : A1h;
        if (Ah_ == nullptr) continue;
        const half* Al_ = s ? A2l : A1l;
        const half* Wh_ = s ? W2h : W1h;
        const half* Wl_ = s ? W2l : W1l;
        const int K     = s ? K2 : K1;
        const int niter = K >> 4;

#pragma unroll
        for (int p = 0; p < 3; ++p) {
            GLOAD(p, p << 4);
            asm volatile("cp.async.commit_group;");
        }
        for (int it0 = 0; it0 < niter; it0 += 4) {
#pragma unroll
            for (int sb = 0; sb < 4; sb++) {
                const int it = it0 + sb;
                const int nx = it + 3;
                constexpr int nlut[4] = {3, 0, 1, 2};
                if (nx < niter) GLOAD(nlut[sb], nx << 4);
                asm volatile("cp.async.commit_group;");
                asm volatile("cp.async.wait_group 3;");
                __syncthreads();
                GMMA(sb);
                __syncthreads();
            }
        }
    }
#undef GLOAD
#undef GMMA

    const int jl2 = 2 * (lane & 3);
#pragma unroll
    for (int hf = 0; hf < 2; hf++) {
        const int r = wm + (lane >> 2) + 8 * hf;
#pragma unroll
        for (int o = 0; o < 2; o++) {
#pragma unroll
            for (int e = 0; e < 2; e++) {
                const int q  = 2 * hf + e;
                const int jg = j0 + 8 * o + jl2 + e;
                float gi = D1[0 + o][q] + D2[0 + o][q] * INV2048;
                float gf = D1[2 + o][q] + D2[2 + o][q] * INV2048;
                float gg = D1[4 + o][q] + D2[4 + o][q] * INV2048;
                float go = D1[6 + o][q] + D2[6 + o][q] * INV2048;
                if (bias1) {
                    gi += bias1[jg];            gf += bias1[HH + jg];
                    gg += bias1[2 * HH + jg];   go += bias1[3 * HH + jg];
                }
                if (bias2) {
                    gi += bias2[jg];            gf += bias2[HH + jg];
                    gg += bias2[2 * HH + jg];   go += bias2[3 * HH + jg];
                }
                if (gin) {
                    const float* gr = gin + (size_t)r * FH;
                    gi += gr[jg];          gf += gr[HH + jg];
                    gg += gr[2 * HH + jg]; go += gr[3 * HH + jg];
                }
                const int idx = r * HH + jg;
                const float cn = sigmoidf_(gf) * c[idx] + sigmoidf_(gi) * tanhf(gg);
                const float hn = sigmoidf_(go) * tanhf(cn);
                c[idx] = cn;
                h[idx] = hn;
                split16(hn, &hph[idx], &hpl[idx]);
            }
        }
    }
}

// ---------------------------------------------------------------------------
// NEW: 32x64 supertile GEMM for the B path (one call per block).
// 64 supertiles: row0=(st>>4)*32, col0=(st&15)*64. Warps 2(M)x4(N).
// Stage: Ah 1024 | Al 1024 | Bh 2048 | Bl 2048 = 6144; x4 stages.
// Fragment/epilogue mapping copied from proven gin0 kernel.
// ---------------------------------------------------------------------------
__device__ void gemm64w_phase(char* dsm, int st,
    const half* __restrict__ A1h, const half* __restrict__ A1l, int lda1,
    const half* __restrict__ B1h, const half* __restrict__ B1l, int ldb1, int K1,
    const half* __restrict__ A2h, const half* __restrict__ A2l, int lda2,
    const half* __restrict__ B2h, const half* __restrict__ B2l, int ldb2, int K2,
    const float* __restrict__ bias,
    float* __restrict__ C, int ldc, int act)
{
    constexpr int STRIDE = 6144;
    const int tid  = threadIdx.x;
    const int lane = tid & 31;
    const int warp = tid >> 5;
    const int wm = (warp >> 2) * 16;
    const int wn = (warp & 3) * 16;
    const int row0 = (st >> 4) * 32;
    const int col0 = (st & 15) * 64;
    const uint32_t sbase = smem_u32(dsm);

    const int ar = wm + ((lane >> 3) & 1) * 8 + (lane & 7);
    const uint32_t aoff = swz(ar, lane >> 4);
    uint32_t boff;
    {
        const int m = lane >> 3;
        const int n = wn + (m >> 1) * 8 + (lane & 7);
        boff = swz(n, m & 1);
    }

    // cp.async mapping: tid<128 -> A (comp=tid>>6, row=(tid&63)>>1, c=tid&1);
    // tid>=128 -> B (row=(tid-128)>>1, c=tid&1; loads hi AND lo).
    const bool isA = tid < 128;
    const int acomp = (tid >> 6) & 1;
    const int arow = (tid & 63) >> 1, ac = tid & 1;
    const uint32_t asw = swz(arow, ac) + (acomp ? 1024u : 0u);
    const int brow = (tid - 128) >> 1, bc = tid & 1;
    const uint32_t bswq = swz(brow, bc);

    float D1[2][4], D2[2][4];
#pragma unroll
    for (int ni = 0; ni < 2; ni++)
#pragma unroll
        for (int q = 0; q < 4; q++) { D1[ni][q] = 0.f; D2[ni][q] = 0.f; }

#define L64(buf_, k0_)                                                           \
    do {                                                                         \
        if (isA) {                                                               \
            const half* ab = acomp ? Al_ : Ah_;                                  \
            cp16cg(dsm + (buf_)*STRIDE + asw,                                    \
                   ab + (size_t)(row0 + arow) * lda + (k0_) + ac * 8);           \
        } else {                                                                 \
            cp16(dsm + (buf_)*STRIDE + 2048 + bswq,                              \
                 Bh_ + (size_t)(col0 + brow) * ldb + (k0_) + bc * 8);            \
            cp16(dsm + (buf_)*STRIDE + 4096 + bswq,                              \
                 Bl_ + (size_t)(col0 + brow) * ldb + (k0_) + bc * 8);            \
        }                                                                        \
    } while (0)

#define M64(buf_)                                                                \
    do {                                                                         \
        const uint32_t stp = sbase + (buf_)*STRIDE;                              \
        uint32_t ah[4], al_[4], bh[4], bl[4];                                    \
        ldm4(ah,  stp + aoff);                                                   \
        ldm4(al_, stp + 1024 + aoff);                                            \
        ldm4(bh,  stp + 2048 + boff);                                            \
        ldm4(bl,  stp + 4096 + boff);                                            \
        _Pragma("unroll")                                                        \
        for (int ni = 0; ni < 2; ni++) {                                         \
            mma_f16(D1[ni], ah,  bh + 2 * ni);                                   \
            mma_f16(D2[ni], ah,  bl + 2 * ni);                                   \
            mma_f16(D2[ni], al_, bh + 2 * ni);                                   \
        }                                                                        \
    } while (0)

    for (int s = 0; s < 2; ++s) {
        const half* Ah_ = s ? A2h : A1h;
        if (Ah_ == nullptr) continue;
        const half* Al_ = s ? A2l : A1l;
        const half* Bh_ = s ? B2h : B1h;
        const half* Bl_ = s ? B2l : B1l;
        const int lda = s ? lda2 : lda1;
        const int ldb = s ? ldb2 : ldb1;
        const int K   = s ? K2 : K1;
        const int niter = K >> 4;

#pragma unroll
        for (int p = 0; p < 3; ++p) {
            L64(p, p << 4);
            asm volatile("cp.async.commit_group;");
        }
        for (int it0 = 0; it0 < niter; it0 += 4) {
#pragma unroll
            for (int sb = 0; sb < 4; sb++) {
                const int it = it0 + sb;
                const int nx = it + 3;
                constexpr int nlut[4] = {3, 0, 1, 2};
                if (nx < niter) L64(nlut[sb], nx << 4);
                asm volatile("cp.async.commit_group;");
                asm volatile("cp.async.wait_group 3;");
                __syncthreads();
                M64(sb);
                __syncthreads();
            }
        }
    }
#undef L64
#undef M64

#pragma unroll
    for (int ni = 0; ni < 2; ni++) {
        const int cc = col0 + wn + ni * 8 + 2 * (lane & 3);
#pragma unroll
        for (int hf = 0; hf < 2; hf++) {
            const int r = row0 + wm + (lane >> 2) + 8 * hf;
            float v0 = D1[ni][2*hf+0] + D2[ni][2*hf+0] * INV2048 + bias[cc];
            float v1 = D1[ni][2*hf+1] + D2[ni][2*hf+1] * INV2048 + bias[cc+1];
            if (act == 1) { v0 = tanhf(v0); v1 = tanhf(v1); }
            *reinterpret_cast<float2*>(&C[(size_t)r * (size_t)ldc + cc]) =
                make_float2(v0, v1);
        }
    }
}

// ---------------------------------------------------------------------------
// Attention phase (R11/12-proven, byte-identical).
// ---------------------------------------------------------------------------
__device__ void attention_phase(char* dsmc,
                                const float* __restrict__ contexts,
                                const float* __restrict__ gamma,
                                half* __restrict__ ctxh,
                                half* __restrict__ ctxl, int b)
{
    float* sg     = reinterpret_cast<float*>(dsmc);
    float* sw     = sg + HH;
    float* red    = sw + SS;
    float* s_stat = red + 8;

    const int tid  = threadIdx.x;
    const int lane = tid & 31;
    const int warp = tid >> 5;
    const float* cb = contexts + (size_t)b * SS * HH;

    for (int j = tid; j < HH; j += 256) sg[j] = __ldcg(&gamma[(size_t)b * HH + j]);
    __syncthreads();

    for (int s = warp; s < SS; s += 8) {
        const float* cr = cb + (size_t)s * HH;
        float sum = 0.0f;
#pragma unroll 4
        for (int j = lane * 4; j < HH; j += 128) {
            float4 v = *reinterpret_cast<const float4*>(&cr[j]);
            sum = fmaf(v.x, sg[j], sum);
            sum = fmaf(v.y, sg[j + 1], sum);
            sum = fmaf(v.z, sg[j + 2], sum);
            sum = fmaf(v.w, sg[j + 3], sum);
        }
#pragma unroll
        for (int off = 16; off; off >>= 1)
            sum += __shfl_xor_sync(0xffffffffu, sum, off);
        if (lane == 0) sw[s] = sum;
    }
    __syncthreads();

    const float v = (tid < SS) ? sw[tid] : -3.4e38f;
    float m = v;
#pragma unroll
    for (int off = 16; off; off >>= 1)
        m = fmaxf(m, __shfl_xor_sync(0xffffffffu, m, off));
    if (lane == 0) red[warp] = m;
    __syncthreads();
    if (tid == 0) {
        float mm = red[0];
        for (int w2 = 1; w2 < 8; w2++) mm = fmaxf(mm, red[w2]);
        *s_stat = mm;
    }
    __syncthreads();
    const float bm = *s_stat;
    const float e = (tid < SS) ? __expf(v - bm) : 0.0f;
    float s2 = e;
#pragma unroll
    for (int off = 16; off; off >>= 1)
        s2 += __shfl_xor_sync(0xffffffffu, s2, off);
    if (lane == 0) red[warp] = s2;
    __syncthreads();
    if (tid == 0) {
        float t = 0.0f;
        for (int w2 = 0; w2 < 8; w2++) t += red[w2];
        *s_stat = 1.0f / t;
    }
    __syncthreads();
    if (tid < SS) sw[tid] = e * (*s_stat);
    __syncthreads();

    float acc[4] = {0.0f, 0.0f, 0.0f, 0.0f};
    for (int s = 0; s < SS; s++) {
        const float w = sw[s];
        const float* cr = cb + (size_t)s * HH;
#pragma unroll
        for (int q = 0; q < 4; q++)
            acc[q] = fmaf(w, cr[tid + q * 256], acc[q]);
    }
#pragma unroll
    for (int q = 0; q < 4; q++) {
        const int idx = b * HH + tid + q * 256;
        split16(acc[q], &ctxh[idx], &ctxl[idx]);
    }
}

// ---------------------------------------------------------------------------
// Persistent kernel: R12 schedule (proven 18.26 ms), B path on supertiles.
//  A (0-63):  P1(t); barA; wait cB>=64(t-1); P2(t); barA; bump cA
//  B (64-127): wait cA>=64(t+1); P3; barB; P4 x2; barB; P5; bump cB
// ---------------------------------------------------------------------------
__global__ __launch_bounds__(256)
void persistent_kernel(const float* __restrict__ b_ih1,
                       const float* __restrict__ b_hh1,
                       const float* __restrict__ attb,
                       const float* __restrict__ outb,
                       const float* __restrict__ contexts,
                       float* __restrict__ out)
{
    extern __shared__ __align__(16) char dsm[];
    const int bid = blockIdx.x;

    half* const h1h[3] = { g_h1hA, g_h1hB, g_h1hC };
    half* const h1l[3] = { g_h1lA, g_h1lB, g_h1lC };

    if (bid < 64) {
        unsigned int tA = 0;
        for (int t = 0; t < TT; t++) {
            // P1: layer-0 gates + cell (in-place h0p update)
            gates64_phase(dsm, bid,
                          g_h0p_h, g_h0p_l, g_Whh0h, g_Whh0l, HH,
                          nullptr, nullptr, nullptr, nullptr, 0,
                          nullptr, nullptr,
                          g_gin0 + (size_t)t * BB * FH,
                          g_h0, g_c0, g_h0p_h, g_h0p_l);
            tA += 64; group_sync(&g_barA, tA);

            // overwrite h1 buf t%3: B's attn(t-3) must be done
            if (t >= 3) wait_cnt(&g_cB, 64u * (unsigned)(t - 2));

            const int rb = (t + 2) % 3;   // (t-1) mod 3
            const int wb = t % 3;
            gates64_phase(dsm, bid,
                          g_h0p_h, g_h0p_l, g_Wih1h, g_Wih1l, HH,
                          h1h[rb], h1l[rb], g_Whh1h, g_Whh1l, HH,
                          b_ih1, b_hh1,
                          nullptr,
                          g_h1, g_c1, h1h[wb], h1l[wb]);
            tA += 64; group_sync(&g_barA, tA);
            bump_cnt(&g_cA);
        }
        float* o2 = out + (size_t)TT * BB * HH;
        for (int idx = bid * 256 + threadIdx.x; idx < BB * HH; idx += 64 * 256) {
            o2[BB * HH + idx]     = g_h1[idx];
            o2[3 * BB * HH + idx] = g_c1[idx];
        }
    } else {
        const int bb = bid - 64;
        unsigned int tB = 0;
        for (int t = 0; t < TT; t++) {
            wait_cnt(&g_cA, 64u * (unsigned)(t + 1));
            const half* rh = h1h[t % 3];
            const half* rl = h1l[t % 3];

            // P3: gamma = h1 @ attW^T + attb  (one 32x64 supertile per block)
            gemm64w_phase(dsm, bb,
                          rh, rl, HH, g_attWh, g_attWl, HH, HH,
                          nullptr, nullptr, 0, nullptr, nullptr, 0, 0,
                          attb, g_gamma, HH, 0);
            tB += 64; group_sync(&g_barB, tB);

            // P4: attention (2 batches per block)
            attention_phase(dsm, contexts, g_gamma, g_ctxh, g_ctxl, bb);
            attention_phase(dsm, contexts, g_gamma, g_ctxh, g_ctxl, bb + 64);
            tB += 64; group_sync(&g_barB, tB);

            // P5: out[t] = tanh([ctx, h1] @ outW^T + outb)
            gemm64w_phase(dsm, bb,
                          g_ctxh, g_ctxl, HH, g_outWh, g_outWl, 2 * HH, HH,
                          rh, rl, HH, g_outWh + HH, g_outWl + HH, 2 * HH, HH,
                          outb, out + (size_t)t * BB * HH, HH, 1);
            bump_cnt(&g_cB);
        }
        float* o2 = out + (size_t)TT * BB * HH;
        for (int idx = bb * 256 + threadIdx.x; idx < BB * HH; idx += 64 * 256) {
            o2[idx]               = g_h0[idx];
            o2[2 * BB * HH + idx] = g_c0[idx];
        }
    }
}

// ---------------------------------------------------------------------------
// Launch: 3 kernels, single stream.
// ---------------------------------------------------------------------------
extern "C" void kernel_launch(void* const* d_in, const int* in_sizes, int n_in,
                              void* d_out, int out_size)
{
    (void)in_sizes; (void)n_in; (void)out_size;

    const int*   inputs   = (const int*)  d_in[0];
    const float* h0       = (const float*)d_in[1];
    const float* c0       = (const float*)d_in[2];
    const float* contexts = (const float*)d_in[3];
    const float* emb      = (const float*)d_in[4];
    const float* W_ih0    = (const float*)d_in[5];
    const float* W_hh0    = (const float*)d_in[6];
    const float* b_ih0    = (const float*)d_in[7];
    const float* b_hh0    = (const float*)d_in[8];
    const float* W_ih1    = (const float*)d_in[9];
    const float* W_hh1    = (const float*)d_in[10];
    const float* b_ih1    = (const float*)d_in[11];
    const float* b_hh1    = (const float*)d_in[12];
    const float* attW     = (const float*)d_in[13];
    const float* attb     = (const float*)d_in[14];
    const float* outW     = (const float*)d_in[15];
    const float* outb     = (const float*)d_in[16];
    float* out = (float*)d_out;

    constexpr int GSMEM = 4 * 12288;   // 49152 (gates64 dominates)
    static bool init_done = false;
    if (!init_done) {
        cudaFuncSetAttribute(persistent_kernel,
                             cudaFuncAttributeMaxDynamicSharedMemorySize, GSMEM);
        init_done = true;
    }

    prologue_kernel<<<1184, 256>>>(emb, W_ih0, W_hh0, W_ih1, W_hh1,
                                   attW, outW, h0, c0);
    {
        dim3 grid(FH / 32, (TT * BB) / 64);
        gin0_gemm_kernel<<<grid, 128>>>(inputs, b_ih0, b_hh0);
    }
    persistent_kernel<<<128, 256, GSMEM>>>(b_ih1, b_hh1, attb, outb,
                                           contexts, out);
}